// round 3
// baseline (speedup 1.0000x reference)
#include <cuda_runtime.h>
#include <math.h>

// ---------------------------------------------------------------------------
// Problem constants: B=4, N=1024, C=1024, H=16, HD=64
// ---------------------------------------------------------------------------

// Scratch buffers (allocation-free rule: __device__ globals)
__device__ float g_t1  [4ULL * 1024 * 1024];   // after qkv seq-linear  (B,N,C)
__device__ float g_qkv [4ULL * 1024 * 3072];   // after qkv chan-linear (B,N,3C)
__device__ float g_attn[4ULL * 1024 * 1024];   // attention output      (B,N,C)
__device__ float g_t2  [4ULL * 1024 * 1024];   // after proj seq-linear (B,N,C)

// ---------------------------------------------------------------------------
// SGEMM 128x128x8, 256 threads, 8x8 register tile per thread,
// double-buffered smem (one __syncthreads per K-iteration).
//   BT=false : C[m,n] = sum_k A[m,k] * B[k,n]          (B row-major KxN)
//   BT=true  : C[m,n] = sum_k A[m,k] * B[n,k]          (B row-major NxK, i.e. W)
//   BIAS_COL=false : + bias[m] ; BIAS_COL=true : + bias[n]
// Batched over blockIdx.z with element strides sA/sB/sC.
// Requires M,N multiples of 128 and K multiple of 8.
// ---------------------------------------------------------------------------
template<bool BT, bool BIAS_COL>
__global__ __launch_bounds__(256)
void sgemm128(const float* __restrict__ A, const float* __restrict__ Bm,
              const float* __restrict__ bias, float* __restrict__ C,
              int M, int N, int K,
              long sA, long sB, long sC)
{
    A  += (long)blockIdx.z * sA;
    Bm += (long)blockIdx.z * sB;
    C  += (long)blockIdx.z * sC;

    __shared__ float As[2][8][128];
    __shared__ float Bs[2][8][128];

    const int tid = threadIdx.x;
    const int m0 = blockIdx.y * 128;
    const int n0 = blockIdx.x * 128;
    const int tm = (tid >> 4) * 8;      // 0..120
    const int tn = (tid & 15) * 8;      // 0..120

    const int lr = tid >> 1;            // 0..127 (tile row for A / NT-B loads)
    const int lc = (tid & 1) * 4;       // 0 or 4 (k sub-col)
    const int br = tid >> 5;            // 0..7   (k row for NN-B load)
    const int bc = (tid & 31) * 4;      // 0..124 (n col for NN-B load)

    float acc[8][8];
    #pragma unroll
    for (int i = 0; i < 8; i++)
        #pragma unroll
        for (int j = 0; j < 8; j++) acc[i][j] = 0.f;

    // Prologue: load k-tile 0 into buffer 0
    {
        float4 av = *(const float4*)(A + (long)(m0 + lr) * K + lc);
        As[0][lc + 0][lr] = av.x; As[0][lc + 1][lr] = av.y;
        As[0][lc + 2][lr] = av.z; As[0][lc + 3][lr] = av.w;
        if (BT) {
            float4 bv = *(const float4*)(Bm + (long)(n0 + lr) * K + lc);
            Bs[0][lc + 0][lr] = bv.x; Bs[0][lc + 1][lr] = bv.y;
            Bs[0][lc + 2][lr] = bv.z; Bs[0][lc + 3][lr] = bv.w;
        } else {
            float4 bv = *(const float4*)(Bm + (long)br * N + (n0 + bc));
            *(float4*)&Bs[0][br][bc] = bv;
        }
    }
    __syncthreads();

    int cur = 0;
    for (int k0 = 0; k0 < K; k0 += 8) {
        const int nxt = cur ^ 1;
        const bool more = (k0 + 8) < K;

        // Prefetch next k-tile from global into registers
        float4 av, bv;
        if (more) {
            av = *(const float4*)(A + (long)(m0 + lr) * K + (k0 + 8 + lc));
            if (BT)
                bv = *(const float4*)(Bm + (long)(n0 + lr) * K + (k0 + 8 + lc));
            else
                bv = *(const float4*)(Bm + (long)(k0 + 8 + br) * N + (n0 + bc));
        }

        // Compute on current buffer
        #pragma unroll
        for (int kk = 0; kk < 8; kk++) {
            float ra[8], rb[8];
            *(float4*)&ra[0] = *(const float4*)&As[cur][kk][tm];
            *(float4*)&ra[4] = *(const float4*)&As[cur][kk][tm + 4];
            *(float4*)&rb[0] = *(const float4*)&Bs[cur][kk][tn];
            *(float4*)&rb[4] = *(const float4*)&Bs[cur][kk][tn + 4];
            #pragma unroll
            for (int i = 0; i < 8; i++)
                #pragma unroll
                for (int j = 0; j < 8; j++)
                    acc[i][j] += ra[i] * rb[j];
        }

        // Stage prefetched tile into the other buffer
        if (more) {
            As[nxt][lc + 0][lr] = av.x; As[nxt][lc + 1][lr] = av.y;
            As[nxt][lc + 2][lr] = av.z; As[nxt][lc + 3][lr] = av.w;
            if (BT) {
                Bs[nxt][lc + 0][lr] = bv.x; Bs[nxt][lc + 1][lr] = bv.y;
                Bs[nxt][lc + 2][lr] = bv.z; Bs[nxt][lc + 3][lr] = bv.w;
            } else {
                *(float4*)&Bs[nxt][br][bc] = bv;
            }
        }
        __syncthreads();
        cur = nxt;
    }

    #pragma unroll
    for (int i = 0; i < 8; i++) {
        const int m = m0 + tm + i;
        const float rowb = BIAS_COL ? 0.f : bias[m];
        #pragma unroll
        for (int j = 0; j < 8; j += 4) {
            float4 o;
            o.x = acc[i][j + 0] + (BIAS_COL ? bias[n0 + tn + j + 0] : rowb);
            o.y = acc[i][j + 1] + (BIAS_COL ? bias[n0 + tn + j + 1] : rowb);
            o.z = acc[i][j + 2] + (BIAS_COL ? bias[n0 + tn + j + 2] : rowb);
            o.w = acc[i][j + 3] + (BIAS_COL ? bias[n0 + tn + j + 3] : rowb);
            *(float4*)(C + (long)m * N + n0 + tn + j) = o;
        }
    }
}

// ---------------------------------------------------------------------------
// Fused attention, flash-style with online softmax.
// One block per (q-chunk of 64 rows, head, batch). 256 threads (16x16),
// each thread owns a 4x4 tile of S / a 4(row)x4(col) tile of O.
// qkv layout: [B][N][3*C] with q at +0, k at +1024, v at +2048, head offset h*64.
// out layout: [B][N][C] (head-major restored: col = h*64 + c)
// ---------------------------------------------------------------------------
#define ATT_LDS 65   // smem row stride (pad to break bank conflicts)

__global__ __launch_bounds__(256)
void attn_kernel(const float* __restrict__ qkv, float* __restrict__ out)
{
    extern __shared__ float sm[];
    float* Qs = sm;                       // 64 x ATT_LDS
    float* Ks = Qs + 64 * ATT_LDS;
    float* Vs = Ks + 64 * ATT_LDS;
    float* Ps = Vs + 64 * ATT_LDS;

    const int qc = blockIdx.x;            // 0..15 (query chunk)
    const int h  = blockIdx.y;            // 0..15
    const int b  = blockIdx.z;            // 0..3
    const int tid = threadIdx.x;
    const int tx = tid & 15, ty = tid >> 4;
    const int n0 = qc * 64;

    const float scale = 0.125f;           // 64^-0.5

    const float* base = qkv + (long)b * 1024 * 3072 + (long)h * 64;

    // Load Q chunk, pre-scaled
    for (int idx = tid; idx < 64 * 64; idx += 256) {
        int r = idx >> 6, d = idx & 63;
        Qs[r * ATT_LDS + d] = base[(long)(n0 + r) * 3072 + d] * scale;
    }

    float m_r[4], l_r[4], acc[4][4];
    #pragma unroll
    for (int i = 0; i < 4; i++) {
        m_r[i] = -1e30f; l_r[i] = 0.f;
        #pragma unroll
        for (int j = 0; j < 4; j++) acc[i][j] = 0.f;
    }

    for (int kc = 0; kc < 16; kc++) {
        __syncthreads();                  // protect Ks/Vs/Ps from previous iter
        const int k0 = kc * 64;
        for (int idx = tid; idx < 64 * 64; idx += 256) {
            int r = idx >> 6, d = idx & 63;
            long row = (long)(k0 + r) * 3072;
            Ks[r * ATT_LDS + d] = base[row + 1024 + d];
            Vs[r * ATT_LDS + d] = base[row + 2048 + d];
        }
        __syncthreads();

        // S = Q * K^T (already scaled via Q)
        float s[4][4];
        #pragma unroll
        for (int i = 0; i < 4; i++)
            #pragma unroll
            for (int j = 0; j < 4; j++) s[i][j] = 0.f;

        #pragma unroll 8
        for (int d = 0; d < 64; d++) {
            float q[4], k[4];
            #pragma unroll
            for (int i = 0; i < 4; i++) q[i] = Qs[(ty * 4 + i) * ATT_LDS + d];
            #pragma unroll
            for (int j = 0; j < 4; j++) k[j] = Ks[(tx * 4 + j) * ATT_LDS + d];
            #pragma unroll
            for (int i = 0; i < 4; i++)
                #pragma unroll
                for (int j = 0; j < 4; j++)
                    s[i][j] += q[i] * k[j];
        }

        // Online softmax per row (reduce across the 16 tx lanes of each row).
        // Lanes sharing a row occupy one 16-lane half of a warp, so xor 1/2/4/8
        // stays within the group.
        #pragma unroll
        for (int i = 0; i < 4; i++) {
            float cm = fmaxf(fmaxf(s[i][0], s[i][1]), fmaxf(s[i][2], s[i][3]));
            cm = fmaxf(cm, __shfl_xor_sync(0xffffffffu, cm, 1));
            cm = fmaxf(cm, __shfl_xor_sync(0xffffffffu, cm, 2));
            cm = fmaxf(cm, __shfl_xor_sync(0xffffffffu, cm, 4));
            cm = fmaxf(cm, __shfl_xor_sync(0xffffffffu, cm, 8));
            float mn = fmaxf(m_r[i], cm);
            float al = __expf(m_r[i] - mn);
            m_r[i] = mn;
            float rs = 0.f;
            #pragma unroll
            for (int j = 0; j < 4; j++) {
                float p = __expf(s[i][j] - mn);
                s[i][j] = p;
                rs += p;
            }
            rs += __shfl_xor_sync(0xffffffffu, rs, 1);
            rs += __shfl_xor_sync(0xffffffffu, rs, 2);
            rs += __shfl_xor_sync(0xffffffffu, rs, 4);
            rs += __shfl_xor_sync(0xffffffffu, rs, 8);
            l_r[i] = l_r[i] * al + rs;
            #pragma unroll
            for (int j = 0; j < 4; j++) acc[i][j] *= al;
            #pragma unroll
            for (int j = 0; j < 4; j++)
                Ps[(ty * 4 + i) * ATT_LDS + tx * 4 + j] = s[i][j];
        }
        __syncthreads();

        // O += P * V
        #pragma unroll 8
        for (int j = 0; j < 64; j++) {
            float p[4], v[4];
            #pragma unroll
            for (int i = 0; i < 4; i++) p[i] = Ps[(ty * 4 + i) * ATT_LDS + j];
            #pragma unroll
            for (int c = 0; c < 4; c++) v[c] = Vs[j * ATT_LDS + tx * 4 + c];
            #pragma unroll
            for (int i = 0; i < 4; i++)
                #pragma unroll
                for (int c = 0; c < 4; c++)
                    acc[i][c] += p[i] * v[c];
        }
    }

    // Normalize and write: out[b][n0 + row][h*64 + col]
    #pragma unroll
    for (int i = 0; i < 4; i++) {
        float inv = 1.f / l_r[i];
        int n = n0 + ty * 4 + i;
        long o = ((long)b * 1024 + n) * 1024 + h * 64 + tx * 4;
        #pragma unroll
        for (int c = 0; c < 4; c++) out[o + c] = acc[i][c] * inv;
    }
}

// ---------------------------------------------------------------------------
// Launch
// ---------------------------------------------------------------------------
extern "C" void kernel_launch(void* const* d_in, const int* in_sizes, int n_in,
                              void* d_out, int out_size)
{
    (void)in_sizes; (void)n_in; (void)out_size;
    const float* x   = (const float*)d_in[0];   // (4,1024,1024)
    const float* Wq0 = (const float*)d_in[1];   // (1024,1024)
    const float* bq0 = (const float*)d_in[2];   // (1024)
    const float* Wq1 = (const float*)d_in[3];   // (3072,1024)
    const float* bq1 = (const float*)d_in[4];   // (3072)
    const float* Wp0 = (const float*)d_in[5];   // (1024,1024)
    const float* bp0 = (const float*)d_in[6];   // (1024)
    const float* Wp1 = (const float*)d_in[7];   // (1024,1024)
    const float* bp1 = (const float*)d_in[8];   // (1024)
    float* out = (float*)d_out;                 // (4,1024,1024)

    float *t1, *qkv, *attn, *t2;
    cudaGetSymbolAddress((void**)&t1,   g_t1);
    cudaGetSymbolAddress((void**)&qkv,  g_qkv);
    cudaGetSymbolAddress((void**)&attn, g_attn);
    cudaGetSymbolAddress((void**)&t2,   g_t2);

    const int attn_smem = 4 * 64 * ATT_LDS * (int)sizeof(float);  // 66560 B
    cudaFuncSetAttribute(attn_kernel,
                         cudaFuncAttributeMaxDynamicSharedMemorySize, attn_smem);

    dim3 blk(256);
    const long P = 1024L * 1024;

    // 1) qkv seq-linear:  t1[b][m][c] = sum_n Wq0[m][n] * x[b][n][c] + bq0[m]
    sgemm128<false, false><<<dim3(8, 8, 4), blk>>>(
        Wq0, x, bq0, t1, 1024, 1024, 1024, 0, P, P);

    // 2) qkv channel-linear (NT): qkv[r][d] = sum_c t1[r][c] * Wq1[d][c] + bq1[d]
    sgemm128<true, true><<<dim3(24, 32, 1), blk>>>(
        t1, Wq1, bq1, qkv, 4096, 3072, 1024, 0, 0, 0);

    // 3) fused attention
    attn_kernel<<<dim3(16, 16, 4), blk, attn_smem>>>(qkv, attn);

    // 4) proj seq-linear
    sgemm128<false, false><<<dim3(8, 8, 4), blk>>>(
        Wp0, attn, bp0, t2, 1024, 1024, 1024, 0, P, P);

    // 5) proj channel-linear (NT) -> final output
    sgemm128<true, true><<<dim3(8, 32, 1), blk>>>(
        t2, Wp1, bp1, out, 4096, 1024, 1024, 0, 0, 0);
}

// round 5
// speedup vs baseline: 1.5140x; 1.5140x over previous
#include <cuda_runtime.h>
#include <cuda_bf16.h>
#include <stdint.h>
#include <math.h>

// ---------------------------------------------------------------------------
// Problem constants: B=4, N=1024, C=1024, H=16, HD=64
// ---------------------------------------------------------------------------

__device__ float g_t1  [4ULL * 1024 * 1024];   // after qkv seq-linear  (B,N,C)
__device__ float g_qkv [4ULL * 1024 * 3072];   // after qkv chan-linear (B,N,3C)
__device__ float g_attn[4ULL * 1024 * 1024];   // attention output      (B,N,C)
__device__ float g_t2  [4ULL * 1024 * 1024];   // after proj seq-linear (B,N,C)

// ---------------------------------------------------------------------------
// Tensor-core GEMM via mma.sync m16n8k16 bf16, fp32 accumulate, bf16x3 split:
//   a = hi + lo (both bf16);  acc += Ahi*Bhi + Ahi*Blo + Alo*Bhi
// Error of dropped lo*lo term ~2^-16 -> fp32-like end-to-end accuracy.
//
//   BT=false : C[m,n] = sum_k A[m,k] * B[k,n]   (B row-major KxN)
//   BT=true  : C[m,n] = sum_k A[m,k] * B[n,k]   (B row-major NxK, i.e. weights)
//   BIAS_COL=false : + bias[m] ; BIAS_COL=true : + bias[n]
// Block tile 128x128x32, 256 threads (8 warps, 2x4 warp grid, 64x32 per warp).
// Double-buffered smem (register prefetch), one __syncthreads per K-tile.
// Requires M,N multiples of 128, K multiple of 32.
// ---------------------------------------------------------------------------

#define LDMX4(r, p) asm volatile( \
    "ldmatrix.sync.aligned.m8n8.x4.shared.b16 {%0,%1,%2,%3}, [%4];" \
    : "=r"((r)[0]), "=r"((r)[1]), "=r"((r)[2]), "=r"((r)[3]) : "r"(p))
#define LDMX2(r, p) asm volatile( \
    "ldmatrix.sync.aligned.m8n8.x2.shared.b16 {%0,%1}, [%2];" \
    : "=r"((r)[0]), "=r"((r)[1]) : "r"(p))
#define LDMX2T(r, p) asm volatile( \
    "ldmatrix.sync.aligned.m8n8.x2.trans.shared.b16 {%0,%1}, [%2];" \
    : "=r"((r)[0]), "=r"((r)[1]) : "r"(p))
#define MMA16816(d, a, b) asm volatile( \
    "mma.sync.aligned.m16n8k16.row.col.f32.bf16.bf16.f32 " \
    "{%0,%1,%2,%3}, {%4,%5,%6,%7}, {%8,%9}, {%0,%1,%2,%3};" \
    : "+f"((d)[0]), "+f"((d)[1]), "+f"((d)[2]), "+f"((d)[3]) \
    : "r"((a)[0]), "r"((a)[1]), "r"((a)[2]), "r"((a)[3]), \
      "r"((b)[0]), "r"((b)[1]))

__device__ __forceinline__ uint32_t cvta_s(const void* p) {
    return (uint32_t)__cvta_generic_to_shared(p);
}

__device__ __forceinline__ void split_bf16(float v, __nv_bfloat16& hi, __nv_bfloat16& lo) {
    hi = __float2bfloat16(v);
    lo = __float2bfloat16(v - __bfloat162float(hi));
}

template<bool BT, bool BIAS_COL>
__global__ __launch_bounds__(256)
void bgemm128(const float* __restrict__ A, const float* __restrict__ Bm,
              const float* __restrict__ bias, float* __restrict__ C,
              int M, int N, int K,
              long sA, long sB, long sC)
{
    A  += (long)blockIdx.z * sA;
    Bm += (long)blockIdx.z * sB;
    C  += (long)blockIdx.z * sC;

    // smem layout (halves), padded strides for conflict-free ldmatrix
    constexpr int A_STR = 40;                    // 32 + 8 pad
    constexpr int B_STR = BT ? 40 : 136;         // NN: 128 + 8 pad
    constexpr int ASZ = 128 * A_STR;
    constexpr int BSZ = BT ? 128 * B_STR : 32 * B_STR;
    constexpr int STG = 2 * ASZ + 2 * BSZ;       // hi+lo for A and B

    extern __shared__ __align__(16) char smem_raw[];
    __nv_bfloat16* sm = (__nv_bfloat16*)smem_raw;

    const int tid  = threadIdx.x;
    const int lane = tid & 31;
    const int warp = tid >> 5;
    const int wm = (warp & 1) * 64;
    const int wn = (warp >> 1) * 32;
    const int m0 = blockIdx.y * 128;
    const int n0 = blockIdx.x * 128;

    // global-load assignments
    const int ar  = tid >> 1;            // A row 0..127
    const int ac  = (tid & 1) * 16;      // A col base (of 32)
    const int br  = BT ? (tid >> 1) : (tid >> 3);   // B row (n or k)
    const int bc  = BT ? ((tid & 1) * 16) : ((tid & 7) * 16);

    float acc[4][4][4];
    #pragma unroll
    for (int i = 0; i < 4; i++)
        #pragma unroll
        for (int j = 0; j < 4; j++)
            #pragma unroll
            for (int e = 0; e < 4; e++) acc[i][j][e] = 0.f;

    float4 av[4], bv[4];

    // ---- prologue: load k-tile 0, convert, store to stage 0 ----
    #pragma unroll
    for (int i = 0; i < 4; i++)
        av[i] = *(const float4*)(A + (long)(m0 + ar) * K + ac + i * 4);
    #pragma unroll
    for (int i = 0; i < 4; i++) {
        if (BT) bv[i] = *(const float4*)(Bm + (long)(n0 + br) * K + bc + i * 4);
        else    bv[i] = *(const float4*)(Bm + (long)br * N + (n0 + bc) + i * 4);
    }
    {
        __nv_bfloat16 *aH = sm, *aL = sm + ASZ, *bH = sm + 2 * ASZ, *bL = bH + BSZ;
        #pragma unroll
        for (int i = 0; i < 4; i++) {
            const float* f = (const float*)&av[i];
            #pragma unroll
            for (int e = 0; e < 4; e++) {
                __nv_bfloat16 h, l; split_bf16(f[e], h, l);
                aH[ar * A_STR + ac + i * 4 + e] = h;
                aL[ar * A_STR + ac + i * 4 + e] = l;
            }
            const float* g = (const float*)&bv[i];
            #pragma unroll
            for (int e = 0; e < 4; e++) {
                __nv_bfloat16 h, l; split_bf16(g[e], h, l);
                bH[br * B_STR + bc + i * 4 + e] = h;
                bL[br * B_STR + bc + i * 4 + e] = l;
            }
        }
    }
    __syncthreads();

    int cur = 0;
    for (int k0 = 0; k0 < K; k0 += 32) {
        const bool more = (k0 + 32) < K;

        // prefetch next k-tile into registers
        if (more) {
            #pragma unroll
            for (int i = 0; i < 4; i++)
                av[i] = *(const float4*)(A + (long)(m0 + ar) * K + (k0 + 32 + ac) + i * 4);
            #pragma unroll
            for (int i = 0; i < 4; i++) {
                if (BT) bv[i] = *(const float4*)(Bm + (long)(n0 + br) * K + (k0 + 32 + bc) + i * 4);
                else    bv[i] = *(const float4*)(Bm + (long)(k0 + 32 + br) * N + (n0 + bc) + i * 4);
            }
        }

        // compute on current stage
        {
            const __nv_bfloat16* aH = sm + cur * STG;
            const __nv_bfloat16* aL = aH + ASZ;
            const __nv_bfloat16* bH = aH + 2 * ASZ;
            const __nv_bfloat16* bL = bH + BSZ;

            #pragma unroll
            for (int ks = 0; ks < 2; ks++) {
                const int kk = ks * 16;
                uint32_t ah[4][4], al[4][4];
                #pragma unroll
                for (int fm = 0; fm < 4; fm++) {
                    const int row = wm + fm * 16 + (lane & 15);
                    const int col = kk + (lane >> 4) * 8;
                    LDMX4(ah[fm], cvta_s(aH + row * A_STR + col));
                    LDMX4(al[fm], cvta_s(aL + row * A_STR + col));
                }
                uint32_t bh[4][2], bl[4][2];
                #pragma unroll
                for (int fn = 0; fn < 4; fn++) {
                    if (BT) {
                        const int row = wn + fn * 8 + (lane & 7);
                        const int col = kk + ((lane >> 3) & 1) * 8;
                        LDMX2 (bh[fn], cvta_s(bH + row * B_STR + col));
                        LDMX2 (bl[fn], cvta_s(bL + row * B_STR + col));
                    } else {
                        const int row = kk + (lane & 7) + ((lane >> 3) & 1) * 8;
                        const int col = wn + fn * 8;
                        LDMX2T(bh[fn], cvta_s(bH + row * B_STR + col));
                        LDMX2T(bl[fn], cvta_s(bL + row * B_STR + col));
                    }
                }
                #pragma unroll
                for (int fm = 0; fm < 4; fm++)
                    #pragma unroll
                    for (int fn = 0; fn < 4; fn++) {
                        MMA16816(acc[fm][fn], ah[fm], bh[fn]);
                        MMA16816(acc[fm][fn], ah[fm], bl[fn]);
                        MMA16816(acc[fm][fn], al[fm], bh[fn]);
                    }
            }
        }

        // store prefetched tile into the other stage
        if (more) {
            const int nxt = cur ^ 1;
            __nv_bfloat16* aH = sm + nxt * STG;
            __nv_bfloat16* aL = aH + ASZ;
            __nv_bfloat16* bH = aH + 2 * ASZ;
            __nv_bfloat16* bL = bH + BSZ;
            #pragma unroll
            for (int i = 0; i < 4; i++) {
                const float* f = (const float*)&av[i];
                #pragma unroll
                for (int e = 0; e < 4; e++) {
                    __nv_bfloat16 h, l; split_bf16(f[e], h, l);
                    aH[ar * A_STR + ac + i * 4 + e] = h;
                    aL[ar * A_STR + ac + i * 4 + e] = l;
                }
                const float* g = (const float*)&bv[i];
                #pragma unroll
                for (int e = 0; e < 4; e++) {
                    __nv_bfloat16 h, l; split_bf16(g[e], h, l);
                    bH[br * B_STR + bc + i * 4 + e] = h;
                    bL[br * B_STR + bc + i * 4 + e] = l;
                }
            }
        }
        __syncthreads();
        cur ^= 1;
    }

    // epilogue: bias + store (fp32)
    #pragma unroll
    for (int fm = 0; fm < 4; fm++) {
        #pragma unroll
        for (int fn = 0; fn < 4; fn++) {
            const int row = m0 + wm + fm * 16 + (lane >> 2);
            const int col = n0 + wn + fn * 8 + (lane & 3) * 2;
            float b0, b1, b0b, b1b;
            if (BIAS_COL) {
                b0 = bias[col]; b1 = bias[col + 1]; b0b = b0; b1b = b1;
            } else {
                b0 = bias[row]; b1 = b0;
                b0b = bias[row + 8]; b1b = b0b;
            }
            float2 o0 = make_float2(acc[fm][fn][0] + b0, acc[fm][fn][1] + b1);
            float2 o1 = make_float2(acc[fm][fn][2] + b0b, acc[fm][fn][3] + b1b);
            *(float2*)(C + (long)row * N + col) = o0;
            *(float2*)(C + (long)(row + 8) * N + col) = o1;
        }
    }
}

// ---------------------------------------------------------------------------
// Fused attention, flash-style with online softmax (fp32 SIMT — unchanged).
// ---------------------------------------------------------------------------
#define ATT_LDS 65

__global__ __launch_bounds__(256)
void attn_kernel(const float* __restrict__ qkv, float* __restrict__ out)
{
    extern __shared__ float smf[];
    float* Qs = smf;
    float* Ks = Qs + 64 * ATT_LDS;
    float* Vs = Ks + 64 * ATT_LDS;
    float* Ps = Vs + 64 * ATT_LDS;

    const int qc = blockIdx.x;
    const int h  = blockIdx.y;
    const int b  = blockIdx.z;
    const int tid = threadIdx.x;
    const int tx = tid & 15, ty = tid >> 4;
    const int n0 = qc * 64;
    const float scale = 0.125f;

    const float* base = qkv + (long)b * 1024 * 3072 + (long)h * 64;

    for (int idx = tid; idx < 64 * 64; idx += 256) {
        int r = idx >> 6, d = idx & 63;
        Qs[r * ATT_LDS + d] = base[(long)(n0 + r) * 3072 + d] * scale;
    }

    float m_r[4], l_r[4], acc[4][4];
    #pragma unroll
    for (int i = 0; i < 4; i++) {
        m_r[i] = -1e30f; l_r[i] = 0.f;
        #pragma unroll
        for (int j = 0; j < 4; j++) acc[i][j] = 0.f;
    }

    for (int kc = 0; kc < 16; kc++) {
        __syncthreads();
        const int k0 = kc * 64;
        for (int idx = tid; idx < 64 * 64; idx += 256) {
            int r = idx >> 6, d = idx & 63;
            long row = (long)(k0 + r) * 3072;
            Ks[r * ATT_LDS + d] = base[row + 1024 + d];
            Vs[r * ATT_LDS + d] = base[row + 2048 + d];
        }
        __syncthreads();

        float s[4][4];
        #pragma unroll
        for (int i = 0; i < 4; i++)
            #pragma unroll
            for (int j = 0; j < 4; j++) s[i][j] = 0.f;

        #pragma unroll 8
        for (int d = 0; d < 64; d++) {
            float q[4], k[4];
            #pragma unroll
            for (int i = 0; i < 4; i++) q[i] = Qs[(ty * 4 + i) * ATT_LDS + d];
            #pragma unroll
            for (int j = 0; j < 4; j++) k[j] = Ks[(tx * 4 + j) * ATT_LDS + d];
            #pragma unroll
            for (int i = 0; i < 4; i++)
                #pragma unroll
                for (int j = 0; j < 4; j++)
                    s[i][j] += q[i] * k[j];
        }

        #pragma unroll
        for (int i = 0; i < 4; i++) {
            float cm = fmaxf(fmaxf(s[i][0], s[i][1]), fmaxf(s[i][2], s[i][3]));
            cm = fmaxf(cm, __shfl_xor_sync(0xffffffffu, cm, 1));
            cm = fmaxf(cm, __shfl_xor_sync(0xffffffffu, cm, 2));
            cm = fmaxf(cm, __shfl_xor_sync(0xffffffffu, cm, 4));
            cm = fmaxf(cm, __shfl_xor_sync(0xffffffffu, cm, 8));
            float mn = fmaxf(m_r[i], cm);
            float al = __expf(m_r[i] - mn);
            m_r[i] = mn;
            float rs = 0.f;
            #pragma unroll
            for (int j = 0; j < 4; j++) {
                float p = __expf(s[i][j] - mn);
                s[i][j] = p;
                rs += p;
            }
            rs += __shfl_xor_sync(0xffffffffu, rs, 1);
            rs += __shfl_xor_sync(0xffffffffu, rs, 2);
            rs += __shfl_xor_sync(0xffffffffu, rs, 4);
            rs += __shfl_xor_sync(0xffffffffu, rs, 8);
            l_r[i] = l_r[i] * al + rs;
            #pragma unroll
            for (int j = 0; j < 4; j++) acc[i][j] *= al;
            #pragma unroll
            for (int j = 0; j < 4; j++)
                Ps[(ty * 4 + i) * ATT_LDS + tx * 4 + j] = s[i][j];
        }
        __syncthreads();

        #pragma unroll 8
        for (int j = 0; j < 64; j++) {
            float p[4], v[4];
            #pragma unroll
            for (int i = 0; i < 4; i++) p[i] = Ps[(ty * 4 + i) * ATT_LDS + j];
            #pragma unroll
            for (int c = 0; c < 4; c++) v[c] = Vs[j * ATT_LDS + tx * 4 + c];
            #pragma unroll
            for (int i = 0; i < 4; i++)
                #pragma unroll
                for (int c = 0; c < 4; c++)
                    acc[i][c] += p[i] * v[c];
        }
    }

    #pragma unroll
    for (int i = 0; i < 4; i++) {
        float inv = 1.f / l_r[i];
        int n = n0 + ty * 4 + i;
        long o = ((long)b * 1024 + n) * 1024 + h * 64 + tx * 4;
        #pragma unroll
        for (int c = 0; c < 4; c++) out[o + c] = acc[i][c] * inv;
    }
}

// ---------------------------------------------------------------------------
// Launch
// ---------------------------------------------------------------------------
extern "C" void kernel_launch(void* const* d_in, const int* in_sizes, int n_in,
                              void* d_out, int out_size)
{
    (void)in_sizes; (void)n_in; (void)out_size;
    const float* x   = (const float*)d_in[0];
    const float* Wq0 = (const float*)d_in[1];
    const float* bq0 = (const float*)d_in[2];
    const float* Wq1 = (const float*)d_in[3];
    const float* bq1 = (const float*)d_in[4];
    const float* Wp0 = (const float*)d_in[5];
    const float* bp0 = (const float*)d_in[6];
    const float* Wp1 = (const float*)d_in[7];
    const float* bp1 = (const float*)d_in[8];
    float* out = (float*)d_out;

    float *t1, *qkv, *attn, *t2;
    cudaGetSymbolAddress((void**)&t1,   g_t1);
    cudaGetSymbolAddress((void**)&qkv,  g_qkv);
    cudaGetSymbolAddress((void**)&attn, g_attn);
    cudaGetSymbolAddress((void**)&t2,   g_t2);

    // dynamic smem: BT stage = 2*(128*40)+2*(128*40) halves; NN uses 136-stride B
    const int smem_bt = (2 * 128 * 40 + 2 * 128 * 40) * 2 * 2;   // 81920
    const int smem_nn = (2 * 128 * 40 + 2 * 32 * 136) * 2 * 2;   // 75776
    cudaFuncSetAttribute(bgemm128<true, true>,
                         cudaFuncAttributeMaxDynamicSharedMemorySize, smem_bt);
    cudaFuncSetAttribute(bgemm128<false, false>,
                         cudaFuncAttributeMaxDynamicSharedMemorySize, smem_nn);

    const int attn_smem = 4 * 64 * ATT_LDS * (int)sizeof(float);
    cudaFuncSetAttribute(attn_kernel,
                         cudaFuncAttributeMaxDynamicSharedMemorySize, attn_smem);

    dim3 blk(256);
    const long P = 1024L * 1024;

    // 1) qkv seq-linear (NN): t1[b] = Wq0 @ x[b] + bq0 (row bias)
    bgemm128<false, false><<<dim3(8, 8, 4), blk, smem_nn>>>(
        Wq0, x, bq0, t1, 1024, 1024, 1024, 0, P, P);

    // 2) qkv channel-linear (BT): qkv = t1 @ Wq1^T + bq1 (col bias)
    bgemm128<true, true><<<dim3(24, 32, 1), blk, smem_bt>>>(
        t1, Wq1, bq1, qkv, 4096, 3072, 1024, 0, 0, 0);

    // 3) fused attention
    attn_kernel<<<dim3(16, 16, 4), blk, attn_smem>>>(qkv, attn);

    // 4) proj seq-linear (NN)
    bgemm128<false, false><<<dim3(8, 8, 4), blk, smem_nn>>>(
        Wp0, attn, bp0, t2, 1024, 1024, 1024, 0, P, P);

    // 5) proj channel-linear (BT) -> final output
    bgemm128<true, true><<<dim3(8, 32, 1), blk, smem_bt>>>(
        t2, Wp1, bp1, out, 4096, 1024, 1024, 0, 0, 0);
}

// round 6
// speedup vs baseline: 2.1018x; 1.3883x over previous
#include <cuda_runtime.h>
#include <cuda_bf16.h>
#include <stdint.h>
#include <math.h>

// ---------------------------------------------------------------------------
// Problem constants: B=4, N=1024, C=1024, H=16, HD=64
// ---------------------------------------------------------------------------

__device__ float g_t1  [4ULL * 1024 * 1024];   // after qkv seq-linear  (B,N,C)
__device__ float g_qkv [4ULL * 1024 * 3072];   // after qkv chan-linear (B,N,3C)
__device__ float g_attn[4ULL * 1024 * 1024];   // attention output      (B,N,C)
__device__ float g_t2  [4ULL * 1024 * 1024];   // after proj seq-linear (B,N,C)

#define LDMX4(r, p) asm volatile( \
    "ldmatrix.sync.aligned.m8n8.x4.shared.b16 {%0,%1,%2,%3}, [%4];" \
    : "=r"((r)[0]), "=r"((r)[1]), "=r"((r)[2]), "=r"((r)[3]) : "r"(p))
#define LDMX2(r, p) asm volatile( \
    "ldmatrix.sync.aligned.m8n8.x2.shared.b16 {%0,%1}, [%2];" \
    : "=r"((r)[0]), "=r"((r)[1]) : "r"(p))
#define LDMX2T(r, p) asm volatile( \
    "ldmatrix.sync.aligned.m8n8.x2.trans.shared.b16 {%0,%1}, [%2];" \
    : "=r"((r)[0]), "=r"((r)[1]) : "r"(p))
#define MMA16816(d, a, b) asm volatile( \
    "mma.sync.aligned.m16n8k16.row.col.f32.bf16.bf16.f32 " \
    "{%0,%1,%2,%3}, {%4,%5,%6,%7}, {%8,%9}, {%0,%1,%2,%3};" \
    : "+f"((d)[0]), "+f"((d)[1]), "+f"((d)[2]), "+f"((d)[3]) \
    : "r"((a)[0]), "r"((a)[1]), "r"((a)[2]), "r"((a)[3]), \
      "r"((b)[0]), "r"((b)[1]))

__device__ __forceinline__ uint32_t cvta_s(const void* p) {
    return (uint32_t)__cvta_generic_to_shared(p);
}

__device__ __forceinline__ void split_bf16(float v, __nv_bfloat16& hi, __nv_bfloat16& lo) {
    hi = __float2bfloat16(v);
    lo = __float2bfloat16(v - __bfloat162float(hi));
}

__device__ __forceinline__ uint32_t pack_bf2(float a, float b) {
    __nv_bfloat162 t = __floats2bfloat162_rn(a, b);
    return *(uint32_t*)&t;
}

// ---------------------------------------------------------------------------
// Tensor-core GEMM (bf16x3 split) — unchanged from R5 (passing, measured).
// ---------------------------------------------------------------------------
template<bool BT, bool BIAS_COL>
__global__ __launch_bounds__(256)
void bgemm128(const float* __restrict__ A, const float* __restrict__ Bm,
              const float* __restrict__ bias, float* __restrict__ C,
              int M, int N, int K,
              long sA, long sB, long sC)
{
    A  += (long)blockIdx.z * sA;
    Bm += (long)blockIdx.z * sB;
    C  += (long)blockIdx.z * sC;

    constexpr int A_STR = 40;
    constexpr int B_STR = BT ? 40 : 136;
    constexpr int ASZ = 128 * A_STR;
    constexpr int BSZ = BT ? 128 * B_STR : 32 * B_STR;
    constexpr int STG = 2 * ASZ + 2 * BSZ;

    extern __shared__ __align__(16) char smem_raw[];
    __nv_bfloat16* sm = (__nv_bfloat16*)smem_raw;

    const int tid  = threadIdx.x;
    const int lane = tid & 31;
    const int warp = tid >> 5;
    const int wm = (warp & 1) * 64;
    const int wn = (warp >> 1) * 32;
    const int m0 = blockIdx.y * 128;
    const int n0 = blockIdx.x * 128;

    const int ar  = tid >> 1;
    const int ac  = (tid & 1) * 16;
    const int br  = BT ? (tid >> 1) : (tid >> 3);
    const int bc  = BT ? ((tid & 1) * 16) : ((tid & 7) * 16);

    float acc[4][4][4];
    #pragma unroll
    for (int i = 0; i < 4; i++)
        #pragma unroll
        for (int j = 0; j < 4; j++)
            #pragma unroll
            for (int e = 0; e < 4; e++) acc[i][j][e] = 0.f;

    float4 av[4], bv[4];

    #pragma unroll
    for (int i = 0; i < 4; i++)
        av[i] = *(const float4*)(A + (long)(m0 + ar) * K + ac + i * 4);
    #pragma unroll
    for (int i = 0; i < 4; i++) {
        if (BT) bv[i] = *(const float4*)(Bm + (long)(n0 + br) * K + bc + i * 4);
        else    bv[i] = *(const float4*)(Bm + (long)br * N + (n0 + bc) + i * 4);
    }
    {
        __nv_bfloat16 *aH = sm, *aL = sm + ASZ, *bH = sm + 2 * ASZ, *bL = bH + BSZ;
        #pragma unroll
        for (int i = 0; i < 4; i++) {
            const float* f = (const float*)&av[i];
            #pragma unroll
            for (int e = 0; e < 4; e++) {
                __nv_bfloat16 h, l; split_bf16(f[e], h, l);
                aH[ar * A_STR + ac + i * 4 + e] = h;
                aL[ar * A_STR + ac + i * 4 + e] = l;
            }
            const float* g = (const float*)&bv[i];
            #pragma unroll
            for (int e = 0; e < 4; e++) {
                __nv_bfloat16 h, l; split_bf16(g[e], h, l);
                bH[br * B_STR + bc + i * 4 + e] = h;
                bL[br * B_STR + bc + i * 4 + e] = l;
            }
        }
    }
    __syncthreads();

    int cur = 0;
    for (int k0 = 0; k0 < K; k0 += 32) {
        const bool more = (k0 + 32) < K;

        if (more) {
            #pragma unroll
            for (int i = 0; i < 4; i++)
                av[i] = *(const float4*)(A + (long)(m0 + ar) * K + (k0 + 32 + ac) + i * 4);
            #pragma unroll
            for (int i = 0; i < 4; i++) {
                if (BT) bv[i] = *(const float4*)(Bm + (long)(n0 + br) * K + (k0 + 32 + bc) + i * 4);
                else    bv[i] = *(const float4*)(Bm + (long)(k0 + 32 + br) * N + (n0 + bc) + i * 4);
            }
        }

        {
            const __nv_bfloat16* aH = sm + cur * STG;
            const __nv_bfloat16* aL = aH + ASZ;
            const __nv_bfloat16* bH = aH + 2 * ASZ;
            const __nv_bfloat16* bL = bH + BSZ;

            #pragma unroll
            for (int ks = 0; ks < 2; ks++) {
                const int kk = ks * 16;
                uint32_t ah[4][4], al[4][4];
                #pragma unroll
                for (int fm = 0; fm < 4; fm++) {
                    const int row = wm + fm * 16 + (lane & 15);
                    const int col = kk + (lane >> 4) * 8;
                    LDMX4(ah[fm], cvta_s(aH + row * A_STR + col));
                    LDMX4(al[fm], cvta_s(aL + row * A_STR + col));
                }
                uint32_t bh[4][2], bl[4][2];
                #pragma unroll
                for (int fn = 0; fn < 4; fn++) {
                    if (BT) {
                        const int row = wn + fn * 8 + (lane & 7);
                        const int col = kk + ((lane >> 3) & 1) * 8;
                        LDMX2 (bh[fn], cvta_s(bH + row * B_STR + col));
                        LDMX2 (bl[fn], cvta_s(bL + row * B_STR + col));
                    } else {
                        const int row = kk + (lane & 7) + ((lane >> 3) & 1) * 8;
                        const int col = wn + fn * 8;
                        LDMX2T(bh[fn], cvta_s(bH + row * B_STR + col));
                        LDMX2T(bl[fn], cvta_s(bL + row * B_STR + col));
                    }
                }
                #pragma unroll
                for (int fm = 0; fm < 4; fm++)
                    #pragma unroll
                    for (int fn = 0; fn < 4; fn++) {
                        MMA16816(acc[fm][fn], ah[fm], bh[fn]);
                        MMA16816(acc[fm][fn], ah[fm], bl[fn]);
                        MMA16816(acc[fm][fn], al[fm], bh[fn]);
                    }
            }
        }

        if (more) {
            const int nxt = cur ^ 1;
            __nv_bfloat16* aH = sm + nxt * STG;
            __nv_bfloat16* aL = aH + ASZ;
            __nv_bfloat16* bH = aH + 2 * ASZ;
            __nv_bfloat16* bL = bH + BSZ;
            #pragma unroll
            for (int i = 0; i < 4; i++) {
                const float* f = (const float*)&av[i];
                #pragma unroll
                for (int e = 0; e < 4; e++) {
                    __nv_bfloat16 h, l; split_bf16(f[e], h, l);
                    aH[ar * A_STR + ac + i * 4 + e] = h;
                    aL[ar * A_STR + ac + i * 4 + e] = l;
                }
                const float* g = (const float*)&bv[i];
                #pragma unroll
                for (int e = 0; e < 4; e++) {
                    __nv_bfloat16 h, l; split_bf16(g[e], h, l);
                    bH[br * B_STR + bc + i * 4 + e] = h;
                    bL[br * B_STR + bc + i * 4 + e] = l;
                }
            }
        }
        __syncthreads();
        cur ^= 1;
    }

    #pragma unroll
    for (int fm = 0; fm < 4; fm++) {
        #pragma unroll
        for (int fn = 0; fn < 4; fn++) {
            const int row = m0 + wm + fm * 16 + (lane >> 2);
            const int col = n0 + wn + fn * 8 + (lane & 3) * 2;
            float b0, b1, b0b, b1b;
            if (BIAS_COL) {
                b0 = bias[col]; b1 = bias[col + 1]; b0b = b0; b1b = b1;
            } else {
                b0 = bias[row]; b1 = b0;
                b0b = bias[row + 8]; b1b = b0b;
            }
            float2 o0 = make_float2(acc[fm][fn][0] + b0, acc[fm][fn][1] + b1);
            float2 o1 = make_float2(acc[fm][fn][2] + b0b, acc[fm][fn][3] + b1b);
            *(float2*)(C + (long)row * N + col) = o0;
            *(float2*)(C + (long)(row + 8) * N + col) = o1;
        }
    }
}

// ---------------------------------------------------------------------------
// Tensor-core flash attention.
// Grid (8, 16, 4) = (q-tile of 128, head, batch). 256 threads = 8 warps.
// Each warp owns 16 q-rows -> softmax stats are warp-local (quad shuffles).
// Precision: QK^T bf16x3 (Q,K split), P plain bf16, V split hi/lo.
// qkv layout: [B][N][3C], q @ +0, k @ +1024, v @ +2048, head offset h*64.
// ---------------------------------------------------------------------------
#define AT_STR 72   // smem row stride in halves (64 + 8 pad)

__global__ __launch_bounds__(256)
void attn_mma(const float* __restrict__ qkv, float* __restrict__ out)
{
    extern __shared__ __align__(16) char smem_raw[];
    __nv_bfloat16* sm = (__nv_bfloat16*)smem_raw;
    constexpr int MSZ = 128 * AT_STR;          // one 128x64 matrix (padded)
    __nv_bfloat16* Qh = sm;
    __nv_bfloat16* Ql = sm + MSZ;
    __nv_bfloat16* Kh = sm + 2 * MSZ;
    __nv_bfloat16* Kl = sm + 3 * MSZ;
    __nv_bfloat16* Vh = sm + 4 * MSZ;
    __nv_bfloat16* Vl = sm + 5 * MSZ;

    const int tid  = threadIdx.x;
    const int lane = tid & 31;
    const int warp = tid >> 5;
    const int qc = blockIdx.x;
    const int h  = blockIdx.y;
    const int b  = blockIdx.z;
    const int n0 = qc * 128;
    const float scale = 0.125f;

    const float* base = qkv + (long)b * 1024 * 3072 + (long)h * 64;

    // ---- load Q tile (scaled, split hi/lo) ----
    for (int idx = tid; idx < 2048; idx += 256) {
        const int r = idx >> 4;
        const int c = (idx & 15) * 4;
        float4 v = *(const float4*)(base + (long)(n0 + r) * 3072 + c);
        const float* f = (const float*)&v;
        #pragma unroll
        for (int e = 0; e < 4; e++) {
            __nv_bfloat16 hi, lo; split_bf16(f[e] * scale, hi, lo);
            Qh[r * AT_STR + c + e] = hi;
            Ql[r * AT_STR + c + e] = lo;
        }
    }
    __syncthreads();

    // ---- preload Q fragments (fixed for whole block) ----
    uint32_t qh[4][4], ql[4][4];
    #pragma unroll
    for (int ks = 0; ks < 4; ks++) {
        const int row = warp * 16 + (lane & 15);
        const int col = ks * 16 + (lane >> 4) * 8;
        LDMX4(qh[ks], cvta_s(Qh + row * AT_STR + col));
        LDMX4(ql[ks], cvta_s(Ql + row * AT_STR + col));
    }

    float o[8][4];
    #pragma unroll
    for (int i = 0; i < 8; i++)
        #pragma unroll
        for (int e = 0; e < 4; e++) o[i][e] = 0.f;
    float mrow[2] = {-1e30f, -1e30f};
    float lrow[2] = {0.f, 0.f};

    for (int kt = 0; kt < 8; kt++) {
        __syncthreads();                       // protect K/V from prev PV
        const int k0 = kt * 128;
        for (int idx = tid; idx < 2048; idx += 256) {
            const int r = idx >> 4;
            const int c = (idx & 15) * 4;
            const float* rowp = base + (long)(k0 + r) * 3072;
            float4 kv = *(const float4*)(rowp + 1024 + c);
            float4 vv = *(const float4*)(rowp + 2048 + c);
            const float* fk = (const float*)&kv;
            const float* fv = (const float*)&vv;
            #pragma unroll
            for (int e = 0; e < 4; e++) {
                __nv_bfloat16 hi, lo;
                split_bf16(fk[e], hi, lo);
                Kh[r * AT_STR + c + e] = hi;
                Kl[r * AT_STR + c + e] = lo;
                split_bf16(fv[e], hi, lo);
                Vh[r * AT_STR + c + e] = hi;
                Vl[r * AT_STR + c + e] = lo;
            }
        }
        __syncthreads();

        // ---- S = Q K^T (bf16x3), warp computes 16 x 128 ----
        float s[16][4];
        #pragma unroll
        for (int fn = 0; fn < 16; fn++)
            #pragma unroll
            for (int e = 0; e < 4; e++) s[fn][e] = 0.f;

        #pragma unroll
        for (int fn = 0; fn < 16; fn++) {
            #pragma unroll
            for (int ks = 0; ks < 4; ks++) {
                uint32_t kh2[2], kl2[2];
                const int row = fn * 8 + (lane & 7);
                const int col = ks * 16 + ((lane >> 3) & 1) * 8;
                LDMX2(kh2, cvta_s(Kh + row * AT_STR + col));
                LDMX2(kl2, cvta_s(Kl + row * AT_STR + col));
                MMA16816(s[fn], qh[ks], kh2);
                MMA16816(s[fn], qh[ks], kl2);
                MMA16816(s[fn], ql[ks], kh2);
            }
        }

        // ---- online softmax (rows warp-local; quad = lanes sharing row) ----
        #pragma unroll
        for (int h2 = 0; h2 < 2; h2++) {
            float mx = mrow[h2];
            #pragma unroll
            for (int fn = 0; fn < 16; fn++)
                mx = fmaxf(mx, fmaxf(s[fn][2 * h2], s[fn][2 * h2 + 1]));
            mx = fmaxf(mx, __shfl_xor_sync(0xffffffffu, mx, 1));
            mx = fmaxf(mx, __shfl_xor_sync(0xffffffffu, mx, 2));
            const float alpha = __expf(mrow[h2] - mx);
            mrow[h2] = mx;
            float sum = 0.f;
            #pragma unroll
            for (int fn = 0; fn < 16; fn++) {
                float p0 = __expf(s[fn][2 * h2] - mx);
                float p1 = __expf(s[fn][2 * h2 + 1] - mx);
                s[fn][2 * h2] = p0; s[fn][2 * h2 + 1] = p1;
                sum += p0 + p1;
            }
            sum += __shfl_xor_sync(0xffffffffu, sum, 1);
            sum += __shfl_xor_sync(0xffffffffu, sum, 2);
            lrow[h2] = lrow[h2] * alpha + sum;
            #pragma unroll
            for (int fn = 0; fn < 8; fn++) {
                o[fn][2 * h2]     *= alpha;
                o[fn][2 * h2 + 1] *= alpha;
            }
        }

        // ---- pack P (C-frag -> A-frag, plain bf16) ----
        uint32_t pk[8][4];
        #pragma unroll
        for (int kf = 0; kf < 8; kf++) {
            pk[kf][0] = pack_bf2(s[2 * kf][0],     s[2 * kf][1]);
            pk[kf][1] = pack_bf2(s[2 * kf][2],     s[2 * kf][3]);
            pk[kf][2] = pack_bf2(s[2 * kf + 1][0], s[2 * kf + 1][1]);
            pk[kf][3] = pack_bf2(s[2 * kf + 1][2], s[2 * kf + 1][3]);
        }

        // ---- O += P V (V split hi/lo) ----
        #pragma unroll
        for (int kf = 0; kf < 8; kf++) {
            const int row = kf * 16 + (lane & 7) + ((lane >> 3) & 1) * 8;
            #pragma unroll
            for (int fn = 0; fn < 8; fn++) {
                uint32_t vh2[2], vl2[2];
                LDMX2T(vh2, cvta_s(Vh + row * AT_STR + fn * 8));
                LDMX2T(vl2, cvta_s(Vl + row * AT_STR + fn * 8));
                MMA16816(o[fn], pk[kf], vh2);
                MMA16816(o[fn], pk[kf], vl2);
            }
        }
    }

    // ---- epilogue: normalize, write out[b][n0+row][h*64 + hd] ----
    const float inv0 = 1.f / lrow[0];
    const float inv1 = 1.f / lrow[1];
    const int r0 = n0 + warp * 16 + (lane >> 2);
    const int cb = h * 64 + (lane & 3) * 2;
    #pragma unroll
    for (int fn = 0; fn < 8; fn++) {
        const int col = cb + fn * 8;
        *(float2*)(out + ((long)b * 1024 + r0) * 1024 + col) =
            make_float2(o[fn][0] * inv0, o[fn][1] * inv0);
        *(float2*)(out + ((long)b * 1024 + r0 + 8) * 1024 + col) =
            make_float2(o[fn][2] * inv1, o[fn][3] * inv1);
    }
}

// ---------------------------------------------------------------------------
// Launch
// ---------------------------------------------------------------------------
extern "C" void kernel_launch(void* const* d_in, const int* in_sizes, int n_in,
                              void* d_out, int out_size)
{
    (void)in_sizes; (void)n_in; (void)out_size;
    const float* x   = (const float*)d_in[0];
    const float* Wq0 = (const float*)d_in[1];
    const float* bq0 = (const float*)d_in[2];
    const float* Wq1 = (const float*)d_in[3];
    const float* bq1 = (const float*)d_in[4];
    const float* Wp0 = (const float*)d_in[5];
    const float* bp0 = (const float*)d_in[6];
    const float* Wp1 = (const float*)d_in[7];
    const float* bp1 = (const float*)d_in[8];
    float* out = (float*)d_out;

    float *t1, *qkv, *attn, *t2;
    cudaGetSymbolAddress((void**)&t1,   g_t1);
    cudaGetSymbolAddress((void**)&qkv,  g_qkv);
    cudaGetSymbolAddress((void**)&attn, g_attn);
    cudaGetSymbolAddress((void**)&t2,   g_t2);

    const int smem_bt = (2 * 128 * 40 + 2 * 128 * 40) * 2 * 2;   // 81920
    const int smem_nn = (2 * 128 * 40 + 2 * 32 * 136) * 2 * 2;   // 75776
    cudaFuncSetAttribute(bgemm128<true, true>,
                         cudaFuncAttributeMaxDynamicSharedMemorySize, smem_bt);
    cudaFuncSetAttribute(bgemm128<false, false>,
                         cudaFuncAttributeMaxDynamicSharedMemorySize, smem_nn);

    const int attn_smem = 6 * 128 * AT_STR * 2;                  // 110592
    cudaFuncSetAttribute(attn_mma,
                         cudaFuncAttributeMaxDynamicSharedMemorySize, attn_smem);

    dim3 blk(256);
    const long P = 1024L * 1024;

    // 1) qkv seq-linear (NN): t1[b] = Wq0 @ x[b] + bq0 (row bias)
    bgemm128<false, false><<<dim3(8, 8, 4), blk, smem_nn>>>(
        Wq0, x, bq0, t1, 1024, 1024, 1024, 0, P, P);

    // 2) qkv channel-linear (BT): qkv = t1 @ Wq1^T + bq1 (col bias)
    bgemm128<true, true><<<dim3(24, 32, 1), blk, smem_bt>>>(
        t1, Wq1, bq1, qkv, 4096, 3072, 1024, 0, 0, 0);

    // 3) tensor-core flash attention
    attn_mma<<<dim3(8, 16, 4), blk, attn_smem>>>(qkv, attn);

    // 4) proj seq-linear (NN)
    bgemm128<false, false><<<dim3(8, 8, 4), blk, smem_nn>>>(
        Wp0, attn, bp0, t2, 1024, 1024, 1024, 0, P, P);

    // 5) proj channel-linear (BT) -> final output
    bgemm128<true, true><<<dim3(8, 32, 1), blk, smem_bt>>>(
        t2, Wp1, bp1, out, 4096, 1024, 1024, 0, 0, 0);
}

// round 9
// speedup vs baseline: 2.6386x; 1.2554x over previous
#include <cuda_runtime.h>
#include <cuda_bf16.h>
#include <stdint.h>
#include <math.h>

// ---------------------------------------------------------------------------
// B=4, N=1024, C=1024, H=16, HD=64
// All GEMM operands live as pre-split bf16 (hi, lo) pairs in global scratch.
// acc += Ah*Bh + Ah*Bl + Al*Bh  (fp32 accum; dropped lo*lo ~2^-16)
// ---------------------------------------------------------------------------

#define M4 (1024 * 1024)

__device__ __nv_bfloat16 g_xh [4ULL * M4], g_xl [4ULL * M4];
__device__ __nv_bfloat16 g_w0h[1ULL * M4], g_w0l[1ULL * M4];
__device__ __nv_bfloat16 g_w1h[3ULL * M4], g_w1l[3ULL * M4];
__device__ __nv_bfloat16 g_p0h[1ULL * M4], g_p0l[1ULL * M4];
__device__ __nv_bfloat16 g_p1h[1ULL * M4], g_p1l[1ULL * M4];
__device__ __nv_bfloat16 g_t1h[4ULL * M4], g_t1l[4ULL * M4];
__device__ __nv_bfloat16 g_qh [12ULL * M4], g_ql [12ULL * M4];
__device__ __nv_bfloat16 g_ah [4ULL * M4], g_al [4ULL * M4];
__device__ __nv_bfloat16 g_t2h[4ULL * M4], g_t2l[4ULL * M4];

#define LDMX4(r, p) asm volatile( \
    "ldmatrix.sync.aligned.m8n8.x4.shared.b16 {%0,%1,%2,%3}, [%4];" \
    : "=r"((r)[0]), "=r"((r)[1]), "=r"((r)[2]), "=r"((r)[3]) : "r"(p))
#define LDMX2(r, p) asm volatile( \
    "ldmatrix.sync.aligned.m8n8.x2.shared.b16 {%0,%1}, [%2];" \
    : "=r"((r)[0]), "=r"((r)[1]) : "r"(p))
#define LDMX2T(r, p) asm volatile( \
    "ldmatrix.sync.aligned.m8n8.x2.trans.shared.b16 {%0,%1}, [%2];" \
    : "=r"((r)[0]), "=r"((r)[1]) : "r"(p))
#define MMA16816(d, a, b) asm volatile( \
    "mma.sync.aligned.m16n8k16.row.col.f32.bf16.bf16.f32 " \
    "{%0,%1,%2,%3}, {%4,%5,%6,%7}, {%8,%9}, {%0,%1,%2,%3};" \
    : "+f"((d)[0]), "+f"((d)[1]), "+f"((d)[2]), "+f"((d)[3]) \
    : "r"((a)[0]), "r"((a)[1]), "r"((a)[2]), "r"((a)[3]), \
      "r"((b)[0]), "r"((b)[1]))
#define CP_COMMIT() asm volatile("cp.async.commit_group;")
#define CP_WAIT(n)  asm volatile("cp.async.wait_group %0;" :: "n"(n))

__device__ __forceinline__ uint32_t cvta_s(const void* p) {
    return (uint32_t)__cvta_generic_to_shared(p);
}
__device__ __forceinline__ void cpa16(uint32_t dst, const void* src) {
    asm volatile("cp.async.ca.shared.global [%0], [%1], 16;" :: "r"(dst), "l"(src));
}
__device__ __forceinline__ void split_bf16(float v, __nv_bfloat16& hi, __nv_bfloat16& lo) {
    hi = __float2bfloat16(v);
    lo = __float2bfloat16(v - __bfloat162float(hi));
}
__device__ __forceinline__ uint32_t pack_bf2(float a, float b) {
    __nv_bfloat162 t = __floats2bfloat162_rn(a, b);
    return *(uint32_t*)&t;
}

// ---------------------------------------------------------------------------
// Pre-split: fp32 -> (hi, lo) bf16
// ---------------------------------------------------------------------------
__global__ __launch_bounds__(256)
void presplit(const float4* __restrict__ in, __nv_bfloat162* __restrict__ h2,
              __nv_bfloat162* __restrict__ l2, int n4)
{
    int i = blockIdx.x * 256 + threadIdx.x;
    if (i >= n4) return;
    float4 v = in[i];
    float f[4] = {v.x, v.y, v.z, v.w};
    __nv_bfloat16 hh[4], ll[4];
    #pragma unroll
    for (int e = 0; e < 4; e++) split_bf16(f[e], hh[e], ll[e]);
    h2[2 * i]     = __halves2bfloat162(hh[0], hh[1]);
    h2[2 * i + 1] = __halves2bfloat162(hh[2], hh[3]);
    l2[2 * i]     = __halves2bfloat162(ll[0], ll[1]);
    l2[2 * i + 1] = __halves2bfloat162(ll[2], ll[3]);
}

// ---------------------------------------------------------------------------
// bf16x3 tensor-core GEMM, cp.async mainloop, pre-split operands.
//   BT=false : C[m,n] = sum_k A[m,k]*B[k,n]  (B KxN row-major)
//   BT=true  : C[m,n] = sum_k A[m,k]*B[n,k]  (B NxK row-major)
//   SPLIT_OUT: write (hi,lo) bf16 pair arrays instead of fp32 C.
// Tile 128x128x32, 8 warps (64x32 each), 2-stage cp.async pipeline.
// ---------------------------------------------------------------------------
template<bool BT, bool BIAS_COL, bool SPLIT_OUT>
__global__ __launch_bounds__(256, 2)
void bgemm(const __nv_bfloat16* __restrict__ Ah, const __nv_bfloat16* __restrict__ Al,
           const __nv_bfloat16* __restrict__ Bh, const __nv_bfloat16* __restrict__ Bl,
           const float* __restrict__ bias, float* __restrict__ C,
           __nv_bfloat16* __restrict__ Ch, __nv_bfloat16* __restrict__ Cl,
           int M, int N, int K, long sA, long sB, long sC)
{
    Ah += (long)blockIdx.z * sA;  Al += (long)blockIdx.z * sA;
    Bh += (long)blockIdx.z * sB;  Bl += (long)blockIdx.z * sB;
    if (SPLIT_OUT) { Ch += (long)blockIdx.z * sC; Cl += (long)blockIdx.z * sC; }
    else           { C  += (long)blockIdx.z * sC; }

    constexpr int A_STR = 40;
    constexpr int B_STR = BT ? 40 : 136;
    constexpr int ASZ = 128 * A_STR;
    constexpr int BSZ = BT ? 128 * B_STR : 32 * B_STR;
    constexpr int STG = 2 * ASZ + 2 * BSZ;

    extern __shared__ __align__(16) __nv_bfloat16 sm[];

    const int tid  = threadIdx.x;
    const int lane = tid & 31;
    const int warp = tid >> 5;
    const int wm = (warp & 1) * 64;
    const int wn = (warp >> 1) * 32;
    const int m0 = blockIdx.y * 128;
    const int n0 = blockIdx.x * 128;

    const int r  = tid >> 1;          // A (and BT-B) row
    const int kc = (tid & 1) * 2;     // chunk pair index (16B chunks)
    const int rb = tid >> 3;          // NN-B k row
    const int cc = (tid & 7) * 2;     // NN-B chunk pair

    // cp.async one k-tile into stage st
    auto issue = [&](int k0, int st) {
        __nv_bfloat16* base = sm + st * STG;
        const __nv_bfloat16* gA  = Ah + (long)(m0 + r) * K + k0 + kc * 8;
        const __nv_bfloat16* gAl = Al + (long)(m0 + r) * K + k0 + kc * 8;
        uint32_t dA  = cvta_s(base + r * A_STR + kc * 8);
        uint32_t dAl = cvta_s(base + ASZ + r * A_STR + kc * 8);
        cpa16(dA, gA);        cpa16(dA + 16, gA + 8);
        cpa16(dAl, gAl);      cpa16(dAl + 16, gAl + 8);
        if (BT) {
            const __nv_bfloat16* gB  = Bh + (long)(n0 + r) * K + k0 + kc * 8;
            const __nv_bfloat16* gBl = Bl + (long)(n0 + r) * K + k0 + kc * 8;
            uint32_t dB  = cvta_s(base + 2 * ASZ + r * B_STR + kc * 8);
            uint32_t dBl = cvta_s(base + 2 * ASZ + BSZ + r * B_STR + kc * 8);
            cpa16(dB, gB);    cpa16(dB + 16, gB + 8);
            cpa16(dBl, gBl);  cpa16(dBl + 16, gBl + 8);
        } else {
            const __nv_bfloat16* gB  = Bh + (long)(k0 + rb) * N + n0 + cc * 8;
            const __nv_bfloat16* gBl = Bl + (long)(k0 + rb) * N + n0 + cc * 8;
            uint32_t dB  = cvta_s(base + 2 * ASZ + rb * B_STR + cc * 8);
            uint32_t dBl = cvta_s(base + 2 * ASZ + BSZ + rb * B_STR + cc * 8);
            cpa16(dB, gB);    cpa16(dB + 16, gB + 8);
            cpa16(dBl, gBl);  cpa16(dBl + 16, gBl + 8);
        }
    };

    float acc[4][4][4];
    #pragma unroll
    for (int i = 0; i < 4; i++)
        #pragma unroll
        for (int j = 0; j < 4; j++)
            #pragma unroll
            for (int e = 0; e < 4; e++) acc[i][j][e] = 0.f;

    issue(0, 0); CP_COMMIT();

    int cur = 0;
    for (int k0 = 0; k0 < K; k0 += 32) {
        const bool more = (k0 + 32) < K;
        if (more) { issue(k0 + 32, cur ^ 1); CP_COMMIT(); }
        if (more) CP_WAIT(1); else CP_WAIT(0);
        __syncthreads();

        const __nv_bfloat16* aH = sm + cur * STG;
        const __nv_bfloat16* aL = aH + ASZ;
        const __nv_bfloat16* bH = aH + 2 * ASZ;
        const __nv_bfloat16* bL = bH + BSZ;

        #pragma unroll
        for (int ks = 0; ks < 2; ks++) {
            const int kk = ks * 16;
            uint32_t ah[4][4], al[4][4];
            #pragma unroll
            for (int fm = 0; fm < 4; fm++) {
                const int row = wm + fm * 16 + (lane & 15);
                const int col = kk + (lane >> 4) * 8;
                LDMX4(ah[fm], cvta_s(aH + row * A_STR + col));
                LDMX4(al[fm], cvta_s(aL + row * A_STR + col));
            }
            #pragma unroll
            for (int fn = 0; fn < 4; fn++) {
                uint32_t bh2[2], bl2[2];
                if (BT) {
                    const int row = wn + fn * 8 + (lane & 7);
                    const int col = kk + ((lane >> 3) & 1) * 8;
                    LDMX2 (bh2, cvta_s(bH + row * B_STR + col));
                    LDMX2 (bl2, cvta_s(bL + row * B_STR + col));
                } else {
                    const int row = kk + (lane & 7) + ((lane >> 3) & 1) * 8;
                    const int col = wn + fn * 8;
                    LDMX2T(bh2, cvta_s(bH + row * B_STR + col));
                    LDMX2T(bl2, cvta_s(bL + row * B_STR + col));
                }
                #pragma unroll
                for (int fm = 0; fm < 4; fm++) {
                    MMA16816(acc[fm][fn], ah[fm], bh2);
                    MMA16816(acc[fm][fn], ah[fm], bl2);
                    MMA16816(acc[fm][fn], al[fm], bh2);
                }
            }
        }
        __syncthreads();
        cur ^= 1;
    }

    // epilogue
    #pragma unroll
    for (int fm = 0; fm < 4; fm++) {
        #pragma unroll
        for (int fn = 0; fn < 4; fn++) {
            const int row = m0 + wm + fm * 16 + (lane >> 2);
            const int col = n0 + wn + fn * 8 + (lane & 3) * 2;
            float b0, b1, b0b, b1b;
            if (BIAS_COL) { b0 = bias[col]; b1 = bias[col + 1]; b0b = b0; b1b = b1; }
            else          { b0 = bias[row]; b1 = b0; b0b = bias[row + 8]; b1b = b0b; }
            float v0 = acc[fm][fn][0] + b0,  v1 = acc[fm][fn][1] + b1;
            float v2 = acc[fm][fn][2] + b0b, v3 = acc[fm][fn][3] + b1b;
            if (SPLIT_OUT) {
                __nv_bfloat16 h0, l0, h1, l1;
                split_bf16(v0, h0, l0); split_bf16(v1, h1, l1);
                *(__nv_bfloat162*)(Ch + (long)row * N + col) = __halves2bfloat162(h0, h1);
                *(__nv_bfloat162*)(Cl + (long)row * N + col) = __halves2bfloat162(l0, l1);
                split_bf16(v2, h0, l0); split_bf16(v3, h1, l1);
                *(__nv_bfloat162*)(Ch + (long)(row + 8) * N + col) = __halves2bfloat162(h0, h1);
                *(__nv_bfloat162*)(Cl + (long)(row + 8) * N + col) = __halves2bfloat162(l0, l1);
            } else {
                *(float2*)(C + (long)row * N + col)       = make_float2(v0, v1);
                *(float2*)(C + (long)(row + 8) * N + col) = make_float2(v2, v3);
            }
        }
    }
}

// ---------------------------------------------------------------------------
// Tensor-core flash attention on pre-split qkv.
// Grid (8,16,4), 8 warps; warp owns 16 q-rows (warp-local softmax).
// K/V cp.async double-buffered. Q pre-scaled by 0.125 (exact in bf16).
// Output written as (hi,lo) bf16 pair.
// ---------------------------------------------------------------------------
#define AT_STR 72
#define AT_MSZ (128 * AT_STR)

__global__ __launch_bounds__(256)
void attn_mma(const __nv_bfloat16* __restrict__ qh_g, const __nv_bfloat16* __restrict__ ql_g,
              __nv_bfloat16* __restrict__ oh, __nv_bfloat16* __restrict__ ol)
{
    extern __shared__ __align__(16) __nv_bfloat16 sm[];
    __nv_bfloat16* Qh = sm;
    __nv_bfloat16* Ql = sm + AT_MSZ;

    const int tid  = threadIdx.x;
    const int lane = tid & 31;
    const int warp = tid >> 5;
    const int qc = blockIdx.x;
    const int h  = blockIdx.y;
    const int b  = blockIdx.z;
    const int n0 = qc * 128;

    const long boff = (long)b * 1024 * 3072 + h * 64;

    // K/V stage st: [Kh][Kl][Vh][Vl], each AT_MSZ halves
    auto issueKV = [&](int kt, int st) {
        __nv_bfloat16* base = sm + 2 * AT_MSZ + st * 4 * AT_MSZ;
        const int k0 = kt * 128;
        #pragma unroll
        for (int j = 0; j < 4; j++) {
            const int idx = j * 256 + tid;
            const int rr = idx >> 3;
            const int c8 = (idx & 7) * 8;
            const long grow = boff + (long)(k0 + rr) * 3072;
            const int soff = rr * AT_STR + c8;
            cpa16(cvta_s(base + soff),               qh_g + grow + 1024 + c8);  // Kh
            cpa16(cvta_s(base + AT_MSZ + soff),      ql_g + grow + 1024 + c8);  // Kl
            cpa16(cvta_s(base + 2 * AT_MSZ + soff),  qh_g + grow + 2048 + c8);  // Vh
            cpa16(cvta_s(base + 3 * AT_MSZ + soff),  ql_g + grow + 2048 + c8);  // Vl
        }
    };

    issueKV(0, 0); CP_COMMIT();

    // Q staging with exact 2^-3 scale
    {
        const __nv_bfloat162 s2 = __floats2bfloat162_rn(0.125f, 0.125f);
        for (int idx = tid; idx < 1024; idx += 256) {
            const int rr = idx >> 3;
            const int c8 = (idx & 7) * 8;
            const long grow = boff + (long)(n0 + rr) * 3072;
            uint4 vh = *(const uint4*)(qh_g + grow + c8);
            uint4 vl = *(const uint4*)(ql_g + grow + c8);
            __nv_bfloat162* ph = (__nv_bfloat162*)&vh;
            __nv_bfloat162* pl = (__nv_bfloat162*)&vl;
            #pragma unroll
            for (int e = 0; e < 4; e++) { ph[e] = __hmul2(ph[e], s2); pl[e] = __hmul2(pl[e], s2); }
            *(uint4*)(Qh + rr * AT_STR + c8) = vh;
            *(uint4*)(Ql + rr * AT_STR + c8) = vl;
        }
    }
    __syncthreads();

    uint32_t qh[4][4], ql[4][4];
    #pragma unroll
    for (int ks = 0; ks < 4; ks++) {
        const int row = warp * 16 + (lane & 15);
        const int col = ks * 16 + (lane >> 4) * 8;
        LDMX4(qh[ks], cvta_s(Qh + row * AT_STR + col));
        LDMX4(ql[ks], cvta_s(Ql + row * AT_STR + col));
    }

    float o[8][4];
    #pragma unroll
    for (int i = 0; i < 8; i++)
        #pragma unroll
        for (int e = 0; e < 4; e++) o[i][e] = 0.f;
    float mrow[2] = {-1e30f, -1e30f};
    float lrow[2] = {0.f, 0.f};

    int st = 0;
    for (int kt = 0; kt < 8; kt++) {
        const bool more = kt < 7;
        if (more) { issueKV(kt + 1, st ^ 1); CP_COMMIT(); }
        if (more) CP_WAIT(1); else CP_WAIT(0);
        __syncthreads();

        const __nv_bfloat16* Kh = sm + 2 * AT_MSZ + st * 4 * AT_MSZ;
        const __nv_bfloat16* Kl = Kh + AT_MSZ;
        const __nv_bfloat16* Vh = Kh + 2 * AT_MSZ;
        const __nv_bfloat16* Vl = Kh + 3 * AT_MSZ;

        float s[16][4];
        #pragma unroll
        for (int fn = 0; fn < 16; fn++)
            #pragma unroll
            for (int e = 0; e < 4; e++) s[fn][e] = 0.f;

        #pragma unroll
        for (int fn = 0; fn < 16; fn++) {
            #pragma unroll
            for (int ks = 0; ks < 4; ks++) {
                uint32_t kh2[2], kl2[2];
                const int row = fn * 8 + (lane & 7);
                const int col = ks * 16 + ((lane >> 3) & 1) * 8;
                LDMX2(kh2, cvta_s(Kh + row * AT_STR + col));
                LDMX2(kl2, cvta_s(Kl + row * AT_STR + col));
                MMA16816(s[fn], qh[ks], kh2);
                MMA16816(s[fn], qh[ks], kl2);
                MMA16816(s[fn], ql[ks], kh2);
            }
        }

        #pragma unroll
        for (int h2 = 0; h2 < 2; h2++) {
            float mx = mrow[h2];
            #pragma unroll
            for (int fn = 0; fn < 16; fn++)
                mx = fmaxf(mx, fmaxf(s[fn][2 * h2], s[fn][2 * h2 + 1]));
            mx = fmaxf(mx, __shfl_xor_sync(0xffffffffu, mx, 1));
            mx = fmaxf(mx, __shfl_xor_sync(0xffffffffu, mx, 2));
            const float alpha = __expf(mrow[h2] - mx);
            mrow[h2] = mx;
            float sum = 0.f;
            #pragma unroll
            for (int fn = 0; fn < 16; fn++) {
                float p0 = __expf(s[fn][2 * h2] - mx);
                float p1 = __expf(s[fn][2 * h2 + 1] - mx);
                s[fn][2 * h2] = p0; s[fn][2 * h2 + 1] = p1;
                sum += p0 + p1;
            }
            sum += __shfl_xor_sync(0xffffffffu, sum, 1);
            sum += __shfl_xor_sync(0xffffffffu, sum, 2);
            lrow[h2] = lrow[h2] * alpha + sum;
            #pragma unroll
            for (int fn = 0; fn < 8; fn++) {
                o[fn][2 * h2]     *= alpha;
                o[fn][2 * h2 + 1] *= alpha;
            }
        }

        uint32_t pk[8][4];
        #pragma unroll
        for (int kf = 0; kf < 8; kf++) {
            pk[kf][0] = pack_bf2(s[2 * kf][0],     s[2 * kf][1]);
            pk[kf][1] = pack_bf2(s[2 * kf][2],     s[2 * kf][3]);
            pk[kf][2] = pack_bf2(s[2 * kf + 1][0], s[2 * kf + 1][1]);
            pk[kf][3] = pack_bf2(s[2 * kf + 1][2], s[2 * kf + 1][3]);
        }

        #pragma unroll
        for (int kf = 0; kf < 8; kf++) {
            const int row = kf * 16 + (lane & 7) + ((lane >> 3) & 1) * 8;
            #pragma unroll
            for (int fn = 0; fn < 8; fn++) {
                uint32_t vh2[2], vl2[2];
                LDMX2T(vh2, cvta_s(Vh + row * AT_STR + fn * 8));
                LDMX2T(vl2, cvta_s(Vl + row * AT_STR + fn * 8));
                MMA16816(o[fn], pk[kf], vh2);
                MMA16816(o[fn], pk[kf], vl2);
            }
        }
        __syncthreads();
        st ^= 1;
    }

    const float inv0 = 1.f / lrow[0];
    const float inv1 = 1.f / lrow[1];
    const int r0 = n0 + warp * 16 + (lane >> 2);
    const int cb = h * 64 + (lane & 3) * 2;
    #pragma unroll
    for (int fn = 0; fn < 8; fn++) {
        const int col = cb + fn * 8;
        float v0 = o[fn][0] * inv0, v1 = o[fn][1] * inv0;
        float v2 = o[fn][2] * inv1, v3 = o[fn][3] * inv1;
        __nv_bfloat16 h0, l0, h1, l1;
        split_bf16(v0, h0, l0); split_bf16(v1, h1, l1);
        *(__nv_bfloat162*)(oh + ((long)b * 1024 + r0) * 1024 + col) = __halves2bfloat162(h0, h1);
        *(__nv_bfloat162*)(ol + ((long)b * 1024 + r0) * 1024 + col) = __halves2bfloat162(l0, l1);
        split_bf16(v2, h0, l0); split_bf16(v3, h1, l1);
        *(__nv_bfloat162*)(oh + ((long)b * 1024 + r0 + 8) * 1024 + col) = __halves2bfloat162(h0, h1);
        *(__nv_bfloat162*)(ol + ((long)b * 1024 + r0 + 8) * 1024 + col) = __halves2bfloat162(l0, l1);
    }
}

// ---------------------------------------------------------------------------
// Launch
// ---------------------------------------------------------------------------
extern "C" void kernel_launch(void* const* d_in, const int* in_sizes, int n_in,
                              void* d_out, int out_size)
{
    (void)in_sizes; (void)n_in; (void)out_size;
    const float* x   = (const float*)d_in[0];
    const float* Wq0 = (const float*)d_in[1];
    const float* bq0 = (const float*)d_in[2];
    const float* Wq1 = (const float*)d_in[3];
    const float* bq1 = (const float*)d_in[4];
    const float* Wp0 = (const float*)d_in[5];
    const float* bp0 = (const float*)d_in[6];
    const float* Wp1 = (const float*)d_in[7];
    const float* bp1 = (const float*)d_in[8];
    float* out = (float*)d_out;

    __nv_bfloat16 *xh, *xl, *w0h, *w0l, *w1h, *w1l, *p0h, *p0l, *p1h, *p1l;
    __nv_bfloat16 *t1h, *t1l, *qh, *ql, *ah, *al, *t2h, *t2l;
    cudaGetSymbolAddress((void**)&xh,  g_xh);  cudaGetSymbolAddress((void**)&xl,  g_xl);
    cudaGetSymbolAddress((void**)&w0h, g_w0h); cudaGetSymbolAddress((void**)&w0l, g_w0l);
    cudaGetSymbolAddress((void**)&w1h, g_w1h); cudaGetSymbolAddress((void**)&w1l, g_w1l);
    cudaGetSymbolAddress((void**)&p0h, g_p0h); cudaGetSymbolAddress((void**)&p0l, g_p0l);
    cudaGetSymbolAddress((void**)&p1h, g_p1h); cudaGetSymbolAddress((void**)&p1l, g_p1l);
    cudaGetSymbolAddress((void**)&t1h, g_t1h); cudaGetSymbolAddress((void**)&t1l, g_t1l);
    cudaGetSymbolAddress((void**)&qh,  g_qh);  cudaGetSymbolAddress((void**)&ql,  g_ql);
    cudaGetSymbolAddress((void**)&ah,  g_ah);  cudaGetSymbolAddress((void**)&al,  g_al);
    cudaGetSymbolAddress((void**)&t2h, g_t2h); cudaGetSymbolAddress((void**)&t2l, g_t2l);

    const int smem_bt = (2 * (2 * 128 * 40 + 2 * 128 * 40)) * 2;   // 81920 B
    const int smem_nn = (2 * (2 * 128 * 40 + 2 * 32 * 136)) * 2;   // 75776 B
    cudaFuncSetAttribute(bgemm<true, true, true>,
                         cudaFuncAttributeMaxDynamicSharedMemorySize, smem_bt);
    cudaFuncSetAttribute(bgemm<true, true, false>,
                         cudaFuncAttributeMaxDynamicSharedMemorySize, smem_bt);
    cudaFuncSetAttribute(bgemm<false, false, true>,
                         cudaFuncAttributeMaxDynamicSharedMemorySize, smem_nn);

    const int attn_smem = 10 * AT_MSZ * 2;                         // 184320 B
    cudaFuncSetAttribute(attn_mma,
                         cudaFuncAttributeMaxDynamicSharedMemorySize, attn_smem);

    dim3 blk(256);
    const long P = 1024L * 1024;

    // 0) pre-split inputs
    presplit<<<4096, blk>>>((const float4*)x,   (__nv_bfloat162*)xh,  (__nv_bfloat162*)xl,  4 * M4 / 4);
    presplit<<<1024, blk>>>((const float4*)Wq0, (__nv_bfloat162*)w0h, (__nv_bfloat162*)w0l, M4 / 4);
    presplit<<<3072, blk>>>((const float4*)Wq1, (__nv_bfloat162*)w1h, (__nv_bfloat162*)w1l, 3 * M4 / 4);
    presplit<<<1024, blk>>>((const float4*)Wp0, (__nv_bfloat162*)p0h, (__nv_bfloat162*)p0l, M4 / 4);
    presplit<<<1024, blk>>>((const float4*)Wp1, (__nv_bfloat162*)p1h, (__nv_bfloat162*)p1l, M4 / 4);

    // 1) qkv seq-linear (NN): t1[b] = Wq0 @ x[b] + bq0
    bgemm<false, false, true><<<dim3(8, 8, 4), blk, smem_nn>>>(
        w0h, w0l, xh, xl, bq0, nullptr, t1h, t1l, 1024, 1024, 1024, 0, P, P);

    // 2) qkv channel-linear (BT): qkv = t1 @ Wq1^T + bq1
    bgemm<true, true, true><<<dim3(24, 32, 1), blk, smem_bt>>>(
        t1h, t1l, w1h, w1l, bq1, nullptr, qh, ql, 4096, 3072, 1024, 0, 0, 0);

    // 3) flash attention
    attn_mma<<<dim3(8, 16, 4), blk, attn_smem>>>(qh, ql, ah, al);

    // 4) proj seq-linear (NN)
    bgemm<false, false, true><<<dim3(8, 8, 4), blk, smem_nn>>>(
        p0h, p0l, ah, al, bp0, nullptr, t2h, t2l, 1024, 1024, 1024, 0, P, P);

    // 5) proj channel-linear (BT) -> fp32 output
    bgemm<true, true, false><<<dim3(8, 32, 1), blk, smem_bt>>>(
        t2h, t2l, p1h, p1l, bp1, out, nullptr, nullptr, 4096, 1024, 1024, 0, 0, 0);
}

// round 11
// speedup vs baseline: 2.7900x; 1.0574x over previous
#include <cuda_runtime.h>
#include <cuda_bf16.h>
#include <stdint.h>
#include <math.h>

// ---------------------------------------------------------------------------
// B=4, N=1024, C=1024, H=16, HD=64
// All GEMM operands live as pre-split bf16 (hi, lo) pairs in global scratch.
// acc += Ah*Bh + Ah*Bl + Al*Bh  (fp32 accum; dropped lo*lo ~2^-16)
// NOTE: harness targets sm_100 (no 'a') — tcgen05 unavailable; mma.sync only.
// ---------------------------------------------------------------------------

#define M4 (1024 * 1024)

__device__ __nv_bfloat16 g_xh [4ULL * M4], g_xl [4ULL * M4];
__device__ __nv_bfloat16 g_w0h[1ULL * M4], g_w0l[1ULL * M4];
__device__ __nv_bfloat16 g_w1h[3ULL * M4], g_w1l[3ULL * M4];
__device__ __nv_bfloat16 g_p0h[1ULL * M4], g_p0l[1ULL * M4];
__device__ __nv_bfloat16 g_p1h[1ULL * M4], g_p1l[1ULL * M4];
__device__ __nv_bfloat16 g_t1h[4ULL * M4], g_t1l[4ULL * M4];
__device__ __nv_bfloat16 g_qh [12ULL * M4], g_ql [12ULL * M4];
__device__ __nv_bfloat16 g_ah [4ULL * M4], g_al [4ULL * M4];
__device__ __nv_bfloat16 g_t2h[4ULL * M4], g_t2l[4ULL * M4];

#define LDMX4(r, p) asm volatile( \
    "ldmatrix.sync.aligned.m8n8.x4.shared.b16 {%0,%1,%2,%3}, [%4];" \
    : "=r"((r)[0]), "=r"((r)[1]), "=r"((r)[2]), "=r"((r)[3]) : "r"(p))
#define LDMX4T(r, p) asm volatile( \
    "ldmatrix.sync.aligned.m8n8.x4.trans.shared.b16 {%0,%1,%2,%3}, [%4];" \
    : "=r"((r)[0]), "=r"((r)[1]), "=r"((r)[2]), "=r"((r)[3]) : "r"(p))
#define LDMX2(r, p) asm volatile( \
    "ldmatrix.sync.aligned.m8n8.x2.shared.b16 {%0,%1}, [%2];" \
    : "=r"((r)[0]), "=r"((r)[1]) : "r"(p))
#define LDMX2T(r, p) asm volatile( \
    "ldmatrix.sync.aligned.m8n8.x2.trans.shared.b16 {%0,%1}, [%2];" \
    : "=r"((r)[0]), "=r"((r)[1]) : "r"(p))
#define MMA16816(d, a, b) asm volatile( \
    "mma.sync.aligned.m16n8k16.row.col.f32.bf16.bf16.f32 " \
    "{%0,%1,%2,%3}, {%4,%5,%6,%7}, {%8,%9}, {%0,%1,%2,%3};" \
    : "+f"((d)[0]), "+f"((d)[1]), "+f"((d)[2]), "+f"((d)[3]) \
    : "r"((a)[0]), "r"((a)[1]), "r"((a)[2]), "r"((a)[3]), \
      "r"((b)[0]), "r"((b)[1]))
#define CP_COMMIT() asm volatile("cp.async.commit_group;")
#define CP_WAIT(n)  asm volatile("cp.async.wait_group %0;" :: "n"(n))

__device__ __forceinline__ uint32_t cvta_s(const void* p) {
    return (uint32_t)__cvta_generic_to_shared(p);
}
__device__ __forceinline__ void cpa16(uint32_t dst, const void* src) {
    asm volatile("cp.async.ca.shared.global [%0], [%1], 16;" :: "r"(dst), "l"(src));
}
__device__ __forceinline__ void split_bf16(float v, __nv_bfloat16& hi, __nv_bfloat16& lo) {
    hi = __float2bfloat16(v);
    lo = __float2bfloat16(v - __bfloat162float(hi));
}
__device__ __forceinline__ uint32_t pack_bf2(float a, float b) {
    __nv_bfloat162 t = __floats2bfloat162_rn(a, b);
    return *(uint32_t*)&t;
}

// ---------------------------------------------------------------------------
// Merged pre-split: one launch covers x, Wq0, Wq1, Wp0, Wp1 (range dispatch)
// Units: float4 (4 fp32). Ranges: x 1048576 | w0 262144 | w1 786432 | p0 262144 | p1 262144
// ---------------------------------------------------------------------------
__global__ __launch_bounds__(256)
void presplit5(const float4* __restrict__ x,  const float4* __restrict__ w0,
               const float4* __restrict__ w1, const float4* __restrict__ p0,
               const float4* __restrict__ p1,
               __nv_bfloat162* __restrict__ xh,  __nv_bfloat162* __restrict__ xl,
               __nv_bfloat162* __restrict__ w0h, __nv_bfloat162* __restrict__ w0l,
               __nv_bfloat162* __restrict__ w1h, __nv_bfloat162* __restrict__ w1l,
               __nv_bfloat162* __restrict__ p0h, __nv_bfloat162* __restrict__ p0l,
               __nv_bfloat162* __restrict__ p1h, __nv_bfloat162* __restrict__ p1l)
{
    long i = (long)blockIdx.x * 256 + threadIdx.x;
    const float4* in; __nv_bfloat162 *oh, *ol; long j;
    if      (i < 1048576) { in = x;  j = i;           oh = xh;  ol = xl;  }
    else if (i < 1310720) { in = w0; j = i - 1048576; oh = w0h; ol = w0l; }
    else if (i < 2097152) { in = w1; j = i - 1310720; oh = w1h; ol = w1l; }
    else if (i < 2359296) { in = p0; j = i - 2097152; oh = p0h; ol = p0l; }
    else                  { in = p1; j = i - 2359296; oh = p1h; ol = p1l; }

    float4 v = in[j];
    float f[4] = {v.x, v.y, v.z, v.w};
    __nv_bfloat16 hh[4], ll[4];
    #pragma unroll
    for (int e = 0; e < 4; e++) split_bf16(f[e], hh[e], ll[e]);
    oh[2 * j]     = __halves2bfloat162(hh[0], hh[1]);
    oh[2 * j + 1] = __halves2bfloat162(hh[2], hh[3]);
    ol[2 * j]     = __halves2bfloat162(ll[0], ll[1]);
    ol[2 * j + 1] = __halves2bfloat162(ll[2], ll[3]);
}

// ---------------------------------------------------------------------------
// bf16x3 tensor-core GEMM, cp.async mainloop, pre-split operands.
//   BT=false : C[m,n] = sum_k A[m,k]*B[k,n]  (B KxN row-major)
//   BT=true  : C[m,n] = sum_k A[m,k]*B[n,k]  (B NxK row-major)
//   SPLIT_OUT: write (hi,lo) bf16 pair arrays instead of fp32 C.
// Tile 128x128x32, 8 warps (64x32 each), 2-stage cp.async pipeline.
// B fragments loaded with x4 ldmatrix (one instr per fn-pair per hi/lo).
// ---------------------------------------------------------------------------
template<bool BT, bool BIAS_COL, bool SPLIT_OUT>
__global__ __launch_bounds__(256, 2)
void bgemm(const __nv_bfloat16* __restrict__ Ah, const __nv_bfloat16* __restrict__ Al,
           const __nv_bfloat16* __restrict__ Bh, const __nv_bfloat16* __restrict__ Bl,
           const float* __restrict__ bias, float* __restrict__ C,
           __nv_bfloat16* __restrict__ Ch, __nv_bfloat16* __restrict__ Cl,
           int M, int N, int K, long sA, long sB, long sC)
{
    Ah += (long)blockIdx.z * sA;  Al += (long)blockIdx.z * sA;
    Bh += (long)blockIdx.z * sB;  Bl += (long)blockIdx.z * sB;
    if (SPLIT_OUT) { Ch += (long)blockIdx.z * sC; Cl += (long)blockIdx.z * sC; }
    else           { C  += (long)blockIdx.z * sC; }

    constexpr int A_STR = 40;
    constexpr int B_STR = BT ? 40 : 136;
    constexpr int ASZ = 128 * A_STR;
    constexpr int BSZ = BT ? 128 * B_STR : 32 * B_STR;
    constexpr int STG = 2 * ASZ + 2 * BSZ;

    extern __shared__ __align__(16) __nv_bfloat16 sm[];

    const int tid  = threadIdx.x;
    const int lane = tid & 31;
    const int warp = tid >> 5;
    const int wm = (warp & 1) * 64;
    const int wn = (warp >> 1) * 32;
    const int m0 = blockIdx.y * 128;
    const int n0 = blockIdx.x * 128;

    const int r  = tid >> 1;          // A (and BT-B) row
    const int kc = (tid & 1) * 2;     // chunk pair index (16B chunks)
    const int rb = tid >> 3;          // NN-B k row
    const int cc = (tid & 7) * 2;     // NN-B chunk pair

    auto issue = [&](int k0, int st) {
        __nv_bfloat16* base = sm + st * STG;
        const __nv_bfloat16* gA  = Ah + (long)(m0 + r) * K + k0 + kc * 8;
        const __nv_bfloat16* gAl = Al + (long)(m0 + r) * K + k0 + kc * 8;
        uint32_t dA  = cvta_s(base + r * A_STR + kc * 8);
        uint32_t dAl = cvta_s(base + ASZ + r * A_STR + kc * 8);
        cpa16(dA, gA);        cpa16(dA + 16, gA + 8);
        cpa16(dAl, gAl);      cpa16(dAl + 16, gAl + 8);
        if (BT) {
            const __nv_bfloat16* gB  = Bh + (long)(n0 + r) * K + k0 + kc * 8;
            const __nv_bfloat16* gBl = Bl + (long)(n0 + r) * K + k0 + kc * 8;
            uint32_t dB  = cvta_s(base + 2 * ASZ + r * B_STR + kc * 8);
            uint32_t dBl = cvta_s(base + 2 * ASZ + BSZ + r * B_STR + kc * 8);
            cpa16(dB, gB);    cpa16(dB + 16, gB + 8);
            cpa16(dBl, gBl);  cpa16(dBl + 16, gBl + 8);
        } else {
            const __nv_bfloat16* gB  = Bh + (long)(k0 + rb) * N + n0 + cc * 8;
            const __nv_bfloat16* gBl = Bl + (long)(k0 + rb) * N + n0 + cc * 8;
            uint32_t dB  = cvta_s(base + 2 * ASZ + rb * B_STR + cc * 8);
            uint32_t dBl = cvta_s(base + 2 * ASZ + BSZ + rb * B_STR + cc * 8);
            cpa16(dB, gB);    cpa16(dB + 16, gB + 8);
            cpa16(dBl, gBl);  cpa16(dBl + 16, gBl + 8);
        }
    };

    float acc[4][4][4];
    #pragma unroll
    for (int i = 0; i < 4; i++)
        #pragma unroll
        for (int j = 0; j < 4; j++)
            #pragma unroll
            for (int e = 0; e < 4; e++) acc[i][j][e] = 0.f;

    issue(0, 0); CP_COMMIT();

    int cur = 0;
    for (int k0 = 0; k0 < K; k0 += 32) {
        const bool more = (k0 + 32) < K;
        if (more) { issue(k0 + 32, cur ^ 1); CP_COMMIT(); }
        if (more) CP_WAIT(1); else CP_WAIT(0);
        __syncthreads();

        const __nv_bfloat16* aH = sm + cur * STG;
        const __nv_bfloat16* aL = aH + ASZ;
        const __nv_bfloat16* bH = aH + 2 * ASZ;
        const __nv_bfloat16* bL = bH + BSZ;

        #pragma unroll
        for (int ks = 0; ks < 2; ks++) {
            const int kk = ks * 16;
            uint32_t ah[4][4], al[4][4];
            #pragma unroll
            for (int fm = 0; fm < 4; fm++) {
                const int row = wm + fm * 16 + (lane & 15);
                const int col = kk + (lane >> 4) * 8;
                LDMX4(ah[fm], cvta_s(aH + row * A_STR + col));
                LDMX4(al[fm], cvta_s(aL + row * A_STR + col));
            }
            // B fragments: one x4 per fn-pair.
            // BT  (K-major): rows = 16 n, cols = 2 k-halves -> m0=b0(fn),m1=b1(fn),m2=b0(fn+1),m3=b1(fn+1)
            // NN  (trans)  : rows = 16 k, cols = 2 n-groups -> same reg->frag mapping
            uint32_t bh4[2][4], bl4[2][4];
            #pragma unroll
            for (int fp = 0; fp < 2; fp++) {
                const int fn = fp * 2;
                if (BT) {
                    const int row = wn + fn * 8 + (lane & 7) + ((lane >> 4) * 8);
                    const int col = kk + ((lane >> 3) & 1) * 8;
                    LDMX4(bh4[fp], cvta_s(bH + row * B_STR + col));
                    LDMX4(bl4[fp], cvta_s(bL + row * B_STR + col));
                } else {
                    const int row = kk + (lane & 7) + (((lane >> 3) & 1) * 8);
                    const int col = wn + fn * 8 + ((lane >> 4) * 8);
                    LDMX4T(bh4[fp], cvta_s(bH + row * B_STR + col));
                    LDMX4T(bl4[fp], cvta_s(bL + row * B_STR + col));
                }
            }
            #pragma unroll
            for (int fn = 0; fn < 4; fn++) {
                const int fp = fn >> 1, hf = (fn & 1) * 2;
                uint32_t bh2[2] = { bh4[fp][hf], bh4[fp][hf + 1] };
                uint32_t bl2[2] = { bl4[fp][hf], bl4[fp][hf + 1] };
                #pragma unroll
                for (int fm = 0; fm < 4; fm++) {
                    MMA16816(acc[fm][fn], ah[fm], bh2);
                    MMA16816(acc[fm][fn], ah[fm], bl2);
                    MMA16816(acc[fm][fn], al[fm], bh2);
                }
            }
        }
        __syncthreads();
        cur ^= 1;
    }

    // epilogue
    #pragma unroll
    for (int fm = 0; fm < 4; fm++) {
        #pragma unroll
        for (int fn = 0; fn < 4; fn++) {
            const int row = m0 + wm + fm * 16 + (lane >> 2);
            const int col = n0 + wn + fn * 8 + (lane & 3) * 2;
            float b0, b1, b0b, b1b;
            if (BIAS_COL) { b0 = bias[col]; b1 = bias[col + 1]; b0b = b0; b1b = b1; }
            else          { b0 = bias[row]; b1 = b0; b0b = bias[row + 8]; b1b = b0b; }
            float v0 = acc[fm][fn][0] + b0,  v1 = acc[fm][fn][1] + b1;
            float v2 = acc[fm][fn][2] + b0b, v3 = acc[fm][fn][3] + b1b;
            if (SPLIT_OUT) {
                __nv_bfloat16 h0, l0, h1, l1;
                split_bf16(v0, h0, l0); split_bf16(v1, h1, l1);
                *(__nv_bfloat162*)(Ch + (long)row * N + col) = __halves2bfloat162(h0, h1);
                *(__nv_bfloat162*)(Cl + (long)row * N + col) = __halves2bfloat162(l0, l1);
                split_bf16(v2, h0, l0); split_bf16(v3, h1, l1);
                *(__nv_bfloat162*)(Ch + (long)(row + 8) * N + col) = __halves2bfloat162(h0, h1);
                *(__nv_bfloat162*)(Cl + (long)(row + 8) * N + col) = __halves2bfloat162(l0, l1);
            } else {
                *(float2*)(C + (long)row * N + col)       = make_float2(v0, v1);
                *(float2*)(C + (long)(row + 8) * N + col) = make_float2(v2, v3);
            }
        }
    }
}

// ---------------------------------------------------------------------------
// Tensor-core flash attention on pre-split qkv (unchanged from R9 passing).
// ---------------------------------------------------------------------------
#define AT_STR 72
#define AT_MSZ (128 * AT_STR)

__global__ __launch_bounds__(256)
void attn_mma(const __nv_bfloat16* __restrict__ qh_g, const __nv_bfloat16* __restrict__ ql_g,
              __nv_bfloat16* __restrict__ oh, __nv_bfloat16* __restrict__ ol)
{
    extern __shared__ __align__(16) __nv_bfloat16 sm[];
    __nv_bfloat16* Qh = sm;
    __nv_bfloat16* Ql = sm + AT_MSZ;

    const int tid  = threadIdx.x;
    const int lane = tid & 31;
    const int warp = tid >> 5;
    const int qc = blockIdx.x;
    const int h  = blockIdx.y;
    const int b  = blockIdx.z;
    const int n0 = qc * 128;

    const long boff = (long)b * 1024 * 3072 + h * 64;

    auto issueKV = [&](int kt, int st) {
        __nv_bfloat16* base = sm + 2 * AT_MSZ + st * 4 * AT_MSZ;
        const int k0 = kt * 128;
        #pragma unroll
        for (int j = 0; j < 4; j++) {
            const int idx = j * 256 + tid;
            const int rr = idx >> 3;
            const int c8 = (idx & 7) * 8;
            const long grow = boff + (long)(k0 + rr) * 3072;
            const int soff = rr * AT_STR + c8;
            cpa16(cvta_s(base + soff),               qh_g + grow + 1024 + c8);
            cpa16(cvta_s(base + AT_MSZ + soff),      ql_g + grow + 1024 + c8);
            cpa16(cvta_s(base + 2 * AT_MSZ + soff),  qh_g + grow + 2048 + c8);
            cpa16(cvta_s(base + 3 * AT_MSZ + soff),  ql_g + grow + 2048 + c8);
        }
    };

    issueKV(0, 0); CP_COMMIT();

    {
        const __nv_bfloat162 s2 = __floats2bfloat162_rn(0.125f, 0.125f);
        for (int idx = tid; idx < 1024; idx += 256) {
            const int rr = idx >> 3;
            const int c8 = (idx & 7) * 8;
            const long grow = boff + (long)(n0 + rr) * 3072;
            uint4 vh = *(const uint4*)(qh_g + grow + c8);
            uint4 vl = *(const uint4*)(ql_g + grow + c8);
            __nv_bfloat162* ph = (__nv_bfloat162*)&vh;
            __nv_bfloat162* pl = (__nv_bfloat162*)&vl;
            #pragma unroll
            for (int e = 0; e < 4; e++) { ph[e] = __hmul2(ph[e], s2); pl[e] = __hmul2(pl[e], s2); }
            *(uint4*)(Qh + rr * AT_STR + c8) = vh;
            *(uint4*)(Ql + rr * AT_STR + c8) = vl;
        }
    }
    __syncthreads();

    uint32_t qh[4][4], ql[4][4];
    #pragma unroll
    for (int ks = 0; ks < 4; ks++) {
        const int row = warp * 16 + (lane & 15);
        const int col = ks * 16 + (lane >> 4) * 8;
        LDMX4(qh[ks], cvta_s(Qh + row * AT_STR + col));
        LDMX4(ql[ks], cvta_s(Ql + row * AT_STR + col));
    }

    float o[8][4];
    #pragma unroll
    for (int i = 0; i < 8; i++)
        #pragma unroll
        for (int e = 0; e < 4; e++) o[i][e] = 0.f;
    float mrow[2] = {-1e30f, -1e30f};
    float lrow[2] = {0.f, 0.f};

    int st = 0;
    for (int kt = 0; kt < 8; kt++) {
        const bool more = kt < 7;
        if (more) { issueKV(kt + 1, st ^ 1); CP_COMMIT(); }
        if (more) CP_WAIT(1); else CP_WAIT(0);
        __syncthreads();

        const __nv_bfloat16* Kh = sm + 2 * AT_MSZ + st * 4 * AT_MSZ;
        const __nv_bfloat16* Kl = Kh + AT_MSZ;
        const __nv_bfloat16* Vh = Kh + 2 * AT_MSZ;
        const __nv_bfloat16* Vl = Kh + 3 * AT_MSZ;

        float s[16][4];
        #pragma unroll
        for (int fn = 0; fn < 16; fn++)
            #pragma unroll
            for (int e = 0; e < 4; e++) s[fn][e] = 0.f;

        #pragma unroll
        for (int fn = 0; fn < 16; fn++) {
            #pragma unroll
            for (int ks = 0; ks < 4; ks++) {
                uint32_t kh2[2], kl2[2];
                const int row = fn * 8 + (lane & 7);
                const int col = ks * 16 + ((lane >> 3) & 1) * 8;
                LDMX2(kh2, cvta_s(Kh + row * AT_STR + col));
                LDMX2(kl2, cvta_s(Kl + row * AT_STR + col));
                MMA16816(s[fn], qh[ks], kh2);
                MMA16816(s[fn], qh[ks], kl2);
                MMA16816(s[fn], ql[ks], kh2);
            }
        }

        #pragma unroll
        for (int h2 = 0; h2 < 2; h2++) {
            float mx = mrow[h2];
            #pragma unroll
            for (int fn = 0; fn < 16; fn++)
                mx = fmaxf(mx, fmaxf(s[fn][2 * h2], s[fn][2 * h2 + 1]));
            mx = fmaxf(mx, __shfl_xor_sync(0xffffffffu, mx, 1));
            mx = fmaxf(mx, __shfl_xor_sync(0xffffffffu, mx, 2));
            const float alpha = __expf(mrow[h2] - mx);
            mrow[h2] = mx;
            float sum = 0.f;
            #pragma unroll
            for (int fn = 0; fn < 16; fn++) {
                float p0 = __expf(s[fn][2 * h2] - mx);
                float p1 = __expf(s[fn][2 * h2 + 1] - mx);
                s[fn][2 * h2] = p0; s[fn][2 * h2 + 1] = p1;
                sum += p0 + p1;
            }
            sum += __shfl_xor_sync(0xffffffffu, sum, 1);
            sum += __shfl_xor_sync(0xffffffffu, sum, 2);
            lrow[h2] = lrow[h2] * alpha + sum;
            #pragma unroll
            for (int fn = 0; fn < 8; fn++) {
                o[fn][2 * h2]     *= alpha;
                o[fn][2 * h2 + 1] *= alpha;
            }
        }

        uint32_t pk[8][4];
        #pragma unroll
        for (int kf = 0; kf < 8; kf++) {
            pk[kf][0] = pack_bf2(s[2 * kf][0],     s[2 * kf][1]);
            pk[kf][1] = pack_bf2(s[2 * kf][2],     s[2 * kf][3]);
            pk[kf][2] = pack_bf2(s[2 * kf + 1][0], s[2 * kf + 1][1]);
            pk[kf][3] = pack_bf2(s[2 * kf + 1][2], s[2 * kf + 1][3]);
        }

        #pragma unroll
        for (int kf = 0; kf < 8; kf++) {
            const int row = kf * 16 + (lane & 7) + ((lane >> 3) & 1) * 8;
            #pragma unroll
            for (int fn = 0; fn < 8; fn++) {
                uint32_t vh2[2], vl2[2];
                LDMX2T(vh2, cvta_s(Vh + row * AT_STR + fn * 8));
                LDMX2T(vl2, cvta_s(Vl + row * AT_STR + fn * 8));
                MMA16816(o[fn], pk[kf], vh2);
                MMA16816(o[fn], pk[kf], vl2);
            }
        }
        __syncthreads();
        st ^= 1;
    }

    const float inv0 = 1.f / lrow[0];
    const float inv1 = 1.f / lrow[1];
    const int r0 = n0 + warp * 16 + (lane >> 2);
    const int cb = h * 64 + (lane & 3) * 2;
    #pragma unroll
    for (int fn = 0; fn < 8; fn++) {
        const int col = cb + fn * 8;
        float v0 = o[fn][0] * inv0, v1 = o[fn][1] * inv0;
        float v2 = o[fn][2] * inv1, v3 = o[fn][3] * inv1;
        __nv_bfloat16 h0, l0, h1, l1;
        split_bf16(v0, h0, l0); split_bf16(v1, h1, l1);
        *(__nv_bfloat162*)(oh + ((long)b * 1024 + r0) * 1024 + col) = __halves2bfloat162(h0, h1);
        *(__nv_bfloat162*)(ol + ((long)b * 1024 + r0) * 1024 + col) = __halves2bfloat162(l0, l1);
        split_bf16(v2, h0, l0); split_bf16(v3, h1, l1);
        *(__nv_bfloat162*)(oh + ((long)b * 1024 + r0 + 8) * 1024 + col) = __halves2bfloat162(h0, h1);
        *(__nv_bfloat162*)(ol + ((long)b * 1024 + r0 + 8) * 1024 + col) = __halves2bfloat162(l0, l1);
    }
}

// ---------------------------------------------------------------------------
// Launch
// ---------------------------------------------------------------------------
extern "C" void kernel_launch(void* const* d_in, const int* in_sizes, int n_in,
                              void* d_out, int out_size)
{
    (void)in_sizes; (void)n_in; (void)out_size;
    const float* x   = (const float*)d_in[0];
    const float* Wq0 = (const float*)d_in[1];
    const float* bq0 = (const float*)d_in[2];
    const float* Wq1 = (const float*)d_in[3];
    const float* bq1 = (const float*)d_in[4];
    const float* Wp0 = (const float*)d_in[5];
    const float* bp0 = (const float*)d_in[6];
    const float* Wp1 = (const float*)d_in[7];
    const float* bp1 = (const float*)d_in[8];
    float* out = (float*)d_out;

    __nv_bfloat16 *xh, *xl, *w0h, *w0l, *w1h, *w1l, *p0h, *p0l, *p1h, *p1l;
    __nv_bfloat16 *t1h, *t1l, *qh, *ql, *ah, *al, *t2h, *t2l;
    cudaGetSymbolAddress((void**)&xh,  g_xh);  cudaGetSymbolAddress((void**)&xl,  g_xl);
    cudaGetSymbolAddress((void**)&w0h, g_w0h); cudaGetSymbolAddress((void**)&w0l, g_w0l);
    cudaGetSymbolAddress((void**)&w1h, g_w1h); cudaGetSymbolAddress((void**)&w1l, g_w1l);
    cudaGetSymbolAddress((void**)&p0h, g_p0h); cudaGetSymbolAddress((void**)&p0l, g_p0l);
    cudaGetSymbolAddress((void**)&p1h, g_p1h); cudaGetSymbolAddress((void**)&p1l, g_p1l);
    cudaGetSymbolAddress((void**)&t1h, g_t1h); cudaGetSymbolAddress((void**)&t1l, g_t1l);
    cudaGetSymbolAddress((void**)&qh,  g_qh);  cudaGetSymbolAddress((void**)&ql,  g_ql);
    cudaGetSymbolAddress((void**)&ah,  g_ah);  cudaGetSymbolAddress((void**)&al,  g_al);
    cudaGetSymbolAddress((void**)&t2h, g_t2h); cudaGetSymbolAddress((void**)&t2l, g_t2l);

    const int smem_bt = (2 * (2 * 128 * 40 + 2 * 128 * 40)) * 2;   // 81920 B
    const int smem_nn = (2 * (2 * 128 * 40 + 2 * 32 * 136)) * 2;   // 75776 B
    cudaFuncSetAttribute(bgemm<true, true, true>,
                         cudaFuncAttributeMaxDynamicSharedMemorySize, smem_bt);
    cudaFuncSetAttribute(bgemm<true, true, false>,
                         cudaFuncAttributeMaxDynamicSharedMemorySize, smem_bt);
    cudaFuncSetAttribute(bgemm<false, false, true>,
                         cudaFuncAttributeMaxDynamicSharedMemorySize, smem_nn);

    const int attn_smem = 10 * AT_MSZ * 2;                         // 184320 B
    cudaFuncSetAttribute(attn_mma,
                         cudaFuncAttributeMaxDynamicSharedMemorySize, attn_smem);

    dim3 blk(256);
    const long P = 1024L * 1024;

    // 0) merged pre-split (x + all four weights), one launch
    presplit5<<<10240, blk>>>((const float4*)x, (const float4*)Wq0, (const float4*)Wq1,
                              (const float4*)Wp0, (const float4*)Wp1,
                              (__nv_bfloat162*)xh,  (__nv_bfloat162*)xl,
                              (__nv_bfloat162*)w0h, (__nv_bfloat162*)w0l,
                              (__nv_bfloat162*)w1h, (__nv_bfloat162*)w1l,
                              (__nv_bfloat162*)p0h, (__nv_bfloat162*)p0l,
                              (__nv_bfloat162*)p1h, (__nv_bfloat162*)p1l);

    // 1) qkv seq-linear (NN): t1[b] = Wq0 @ x[b] + bq0
    bgemm<false, false, true><<<dim3(8, 8, 4), blk, smem_nn>>>(
        w0h, w0l, xh, xl, bq0, nullptr, t1h, t1l, 1024, 1024, 1024, 0, P, P);

    // 2) qkv channel-linear (BT): qkv = t1 @ Wq1^T + bq1
    bgemm<true, true, true><<<dim3(24, 32, 1), blk, smem_bt>>>(
        t1h, t1l, w1h, w1l, bq1, nullptr, qh, ql, 4096, 3072, 1024, 0, 0, 0);

    // 3) flash attention
    attn_mma<<<dim3(8, 16, 4), blk, attn_smem>>>(qh, ql, ah, al);

    // 4) proj seq-linear (NN)
    bgemm<false, false, true><<<dim3(8, 8, 4), blk, smem_nn>>>(
        p0h, p0l, ah, al, bp0, nullptr, t2h, t2l, 1024, 1024, 1024, 0, P, P);

    // 5) proj channel-linear (BT) -> fp32 output
    bgemm<true, true, false><<<dim3(8, 32, 1), blk, smem_bt>>>(
        t2h, t2l, p1h, p1l, bp1, out, nullptr, nullptr, 4096, 1024, 1024, 0, 0, 0);
}

// round 13
// speedup vs baseline: 2.8666x; 1.0275x over previous
#include <cuda_runtime.h>
#include <cuda_bf16.h>
#include <stdint.h>
#include <math.h>

// ---------------------------------------------------------------------------
// B=4, N=1024, C=1024, H=16, HD=64
// All GEMM operands live as pre-split bf16 (hi, lo) pairs in global scratch.
// acc += Ah*Bh + Ah*Bl + Al*Bh  (fp32 accum; dropped lo*lo ~2^-16)
// NOTE: harness targets sm_100 (no 'a') — tcgen05 unavailable; mma.sync only.
// ---------------------------------------------------------------------------

#define M4 (1024 * 1024)

__device__ __nv_bfloat16 g_xh [4ULL * M4], g_xl [4ULL * M4];
__device__ __nv_bfloat16 g_w0h[1ULL * M4], g_w0l[1ULL * M4];
__device__ __nv_bfloat16 g_w1h[3ULL * M4], g_w1l[3ULL * M4];
__device__ __nv_bfloat16 g_p0h[1ULL * M4], g_p0l[1ULL * M4];
__device__ __nv_bfloat16 g_p1h[1ULL * M4], g_p1l[1ULL * M4];
__device__ __nv_bfloat16 g_t1h[4ULL * M4], g_t1l[4ULL * M4];
__device__ __nv_bfloat16 g_qh [12ULL * M4], g_ql [12ULL * M4];
__device__ __nv_bfloat16 g_ah [4ULL * M4], g_al [4ULL * M4];
__device__ __nv_bfloat16 g_t2h[4ULL * M4], g_t2l[4ULL * M4];

#define LDMX4(r, p) asm volatile( \
    "ldmatrix.sync.aligned.m8n8.x4.shared.b16 {%0,%1,%2,%3}, [%4];" \
    : "=r"((r)[0]), "=r"((r)[1]), "=r"((r)[2]), "=r"((r)[3]) : "r"(p))
#define LDMX4T(r, p) asm volatile( \
    "ldmatrix.sync.aligned.m8n8.x4.trans.shared.b16 {%0,%1,%2,%3}, [%4];" \
    : "=r"((r)[0]), "=r"((r)[1]), "=r"((r)[2]), "=r"((r)[3]) : "r"(p))
#define LDMX2(r, p) asm volatile( \
    "ldmatrix.sync.aligned.m8n8.x2.shared.b16 {%0,%1}, [%2];" \
    : "=r"((r)[0]), "=r"((r)[1]) : "r"(p))
#define LDMX2T(r, p) asm volatile( \
    "ldmatrix.sync.aligned.m8n8.x2.trans.shared.b16 {%0,%1}, [%2];" \
    : "=r"((r)[0]), "=r"((r)[1]) : "r"(p))
#define MMA16816(d, a, b) asm volatile( \
    "mma.sync.aligned.m16n8k16.row.col.f32.bf16.bf16.f32 " \
    "{%0,%1,%2,%3}, {%4,%5,%6,%7}, {%8,%9}, {%0,%1,%2,%3};" \
    : "+f"((d)[0]), "+f"((d)[1]), "+f"((d)[2]), "+f"((d)[3]) \
    : "r"((a)[0]), "r"((a)[1]), "r"((a)[2]), "r"((a)[3]), \
      "r"((b)[0]), "r"((b)[1]))
#define CP_COMMIT() asm volatile("cp.async.commit_group;")
#define CP_WAIT(n)  asm volatile("cp.async.wait_group %0;" :: "n"(n))

__device__ __forceinline__ uint32_t cvta_s(const void* p) {
    return (uint32_t)__cvta_generic_to_shared(p);
}
__device__ __forceinline__ void cpa16(uint32_t dst, const void* src) {
    asm volatile("cp.async.ca.shared.global [%0], [%1], 16;" :: "r"(dst), "l"(src));
}
__device__ __forceinline__ void split_bf16(float v, __nv_bfloat16& hi, __nv_bfloat16& lo) {
    hi = __float2bfloat16(v);
    lo = __float2bfloat16(v - __bfloat162float(hi));
}
__device__ __forceinline__ uint32_t pack_bf2(float a, float b) {
    __nv_bfloat162 t = __floats2bfloat162_rn(a, b);
    return *(uint32_t*)&t;
}

// ---------------------------------------------------------------------------
// Merged pre-split: one launch covers x, Wq0, Wq1, Wp0, Wp1 (range dispatch)
// ---------------------------------------------------------------------------
__global__ __launch_bounds__(256)
void presplit5(const float4* __restrict__ x,  const float4* __restrict__ w0,
               const float4* __restrict__ w1, const float4* __restrict__ p0,
               const float4* __restrict__ p1,
               __nv_bfloat162* __restrict__ xh,  __nv_bfloat162* __restrict__ xl,
               __nv_bfloat162* __restrict__ w0h, __nv_bfloat162* __restrict__ w0l,
               __nv_bfloat162* __restrict__ w1h, __nv_bfloat162* __restrict__ w1l,
               __nv_bfloat162* __restrict__ p0h, __nv_bfloat162* __restrict__ p0l,
               __nv_bfloat162* __restrict__ p1h, __nv_bfloat162* __restrict__ p1l)
{
    long i = (long)blockIdx.x * 256 + threadIdx.x;
    const float4* in; __nv_bfloat162 *oh, *ol; long j;
    if      (i < 1048576) { in = x;  j = i;           oh = xh;  ol = xl;  }
    else if (i < 1310720) { in = w0; j = i - 1048576; oh = w0h; ol = w0l; }
    else if (i < 2097152) { in = w1; j = i - 1310720; oh = w1h; ol = w1l; }
    else if (i < 2359296) { in = p0; j = i - 2097152; oh = p0h; ol = p0l; }
    else                  { in = p1; j = i - 2359296; oh = p1h; ol = p1l; }

    float4 v = in[j];
    float f[4] = {v.x, v.y, v.z, v.w};
    __nv_bfloat16 hh[4], ll[4];
    #pragma unroll
    for (int e = 0; e < 4; e++) split_bf16(f[e], hh[e], ll[e]);
    oh[2 * j]     = __halves2bfloat162(hh[0], hh[1]);
    oh[2 * j + 1] = __halves2bfloat162(hh[2], hh[3]);
    ol[2 * j]     = __halves2bfloat162(ll[0], ll[1]);
    ol[2 * j + 1] = __halves2bfloat162(ll[2], ll[3]);
}

// ---------------------------------------------------------------------------
// bf16x3 tensor-core GEMM (unchanged from R11 passing version).
// ---------------------------------------------------------------------------
template<bool BT, bool BIAS_COL, bool SPLIT_OUT>
__global__ __launch_bounds__(256, 2)
void bgemm(const __nv_bfloat16* __restrict__ Ah, const __nv_bfloat16* __restrict__ Al,
           const __nv_bfloat16* __restrict__ Bh, const __nv_bfloat16* __restrict__ Bl,
           const float* __restrict__ bias, float* __restrict__ C,
           __nv_bfloat16* __restrict__ Ch, __nv_bfloat16* __restrict__ Cl,
           int M, int N, int K, long sA, long sB, long sC)
{
    Ah += (long)blockIdx.z * sA;  Al += (long)blockIdx.z * sA;
    Bh += (long)blockIdx.z * sB;  Bl += (long)blockIdx.z * sB;
    if (SPLIT_OUT) { Ch += (long)blockIdx.z * sC; Cl += (long)blockIdx.z * sC; }
    else           { C  += (long)blockIdx.z * sC; }

    constexpr int A_STR = 40;
    constexpr int B_STR = BT ? 40 : 136;
    constexpr int ASZ = 128 * A_STR;
    constexpr int BSZ = BT ? 128 * B_STR : 32 * B_STR;
    constexpr int STG = 2 * ASZ + 2 * BSZ;

    extern __shared__ __align__(16) __nv_bfloat16 sm[];

    const int tid  = threadIdx.x;
    const int lane = tid & 31;
    const int warp = tid >> 5;
    const int wm = (warp & 1) * 64;
    const int wn = (warp >> 1) * 32;
    const int m0 = blockIdx.y * 128;
    const int n0 = blockIdx.x * 128;

    const int r  = tid >> 1;
    const int kc = (tid & 1) * 2;
    const int rb = tid >> 3;
    const int cc = (tid & 7) * 2;

    auto issue = [&](int k0, int st) {
        __nv_bfloat16* base = sm + st * STG;
        const __nv_bfloat16* gA  = Ah + (long)(m0 + r) * K + k0 + kc * 8;
        const __nv_bfloat16* gAl = Al + (long)(m0 + r) * K + k0 + kc * 8;
        uint32_t dA  = cvta_s(base + r * A_STR + kc * 8);
        uint32_t dAl = cvta_s(base + ASZ + r * A_STR + kc * 8);
        cpa16(dA, gA);        cpa16(dA + 16, gA + 8);
        cpa16(dAl, gAl);      cpa16(dAl + 16, gAl + 8);
        if (BT) {
            const __nv_bfloat16* gB  = Bh + (long)(n0 + r) * K + k0 + kc * 8;
            const __nv_bfloat16* gBl = Bl + (long)(n0 + r) * K + k0 + kc * 8;
            uint32_t dB  = cvta_s(base + 2 * ASZ + r * B_STR + kc * 8);
            uint32_t dBl = cvta_s(base + 2 * ASZ + BSZ + r * B_STR + kc * 8);
            cpa16(dB, gB);    cpa16(dB + 16, gB + 8);
            cpa16(dBl, gBl);  cpa16(dBl + 16, gBl + 8);
        } else {
            const __nv_bfloat16* gB  = Bh + (long)(k0 + rb) * N + n0 + cc * 8;
            const __nv_bfloat16* gBl = Bl + (long)(k0 + rb) * N + n0 + cc * 8;
            uint32_t dB  = cvta_s(base + 2 * ASZ + rb * B_STR + cc * 8);
            uint32_t dBl = cvta_s(base + 2 * ASZ + BSZ + rb * B_STR + cc * 8);
            cpa16(dB, gB);    cpa16(dB + 16, gB + 8);
            cpa16(dBl, gBl);  cpa16(dBl + 16, gBl + 8);
        }
    };

    float acc[4][4][4];
    #pragma unroll
    for (int i = 0; i < 4; i++)
        #pragma unroll
        for (int j = 0; j < 4; j++)
            #pragma unroll
            for (int e = 0; e < 4; e++) acc[i][j][e] = 0.f;

    issue(0, 0); CP_COMMIT();

    int cur = 0;
    for (int k0 = 0; k0 < K; k0 += 32) {
        const bool more = (k0 + 32) < K;
        if (more) { issue(k0 + 32, cur ^ 1); CP_COMMIT(); }
        if (more) CP_WAIT(1); else CP_WAIT(0);
        __syncthreads();

        const __nv_bfloat16* aH = sm + cur * STG;
        const __nv_bfloat16* aL = aH + ASZ;
        const __nv_bfloat16* bH = aH + 2 * ASZ;
        const __nv_bfloat16* bL = bH + BSZ;

        #pragma unroll
        for (int ks = 0; ks < 2; ks++) {
            const int kk = ks * 16;
            uint32_t ah[4][4], al[4][4];
            #pragma unroll
            for (int fm = 0; fm < 4; fm++) {
                const int row = wm + fm * 16 + (lane & 15);
                const int col = kk + (lane >> 4) * 8;
                LDMX4(ah[fm], cvta_s(aH + row * A_STR + col));
                LDMX4(al[fm], cvta_s(aL + row * A_STR + col));
            }
            uint32_t bh4[2][4], bl4[2][4];
            #pragma unroll
            for (int fp = 0; fp < 2; fp++) {
                const int fn = fp * 2;
                if (BT) {
                    const int row = wn + fn * 8 + (lane & 7) + ((lane >> 4) * 8);
                    const int col = kk + ((lane >> 3) & 1) * 8;
                    LDMX4(bh4[fp], cvta_s(bH + row * B_STR + col));
                    LDMX4(bl4[fp], cvta_s(bL + row * B_STR + col));
                } else {
                    const int row = kk + (lane & 7) + (((lane >> 3) & 1) * 8);
                    const int col = wn + fn * 8 + ((lane >> 4) * 8);
                    LDMX4T(bh4[fp], cvta_s(bH + row * B_STR + col));
                    LDMX4T(bl4[fp], cvta_s(bL + row * B_STR + col));
                }
            }
            #pragma unroll
            for (int fn = 0; fn < 4; fn++) {
                const int fp = fn >> 1, hf = (fn & 1) * 2;
                uint32_t bh2[2] = { bh4[fp][hf], bh4[fp][hf + 1] };
                uint32_t bl2[2] = { bl4[fp][hf], bl4[fp][hf + 1] };
                #pragma unroll
                for (int fm = 0; fm < 4; fm++) {
                    MMA16816(acc[fm][fn], ah[fm], bh2);
                    MMA16816(acc[fm][fn], ah[fm], bl2);
                    MMA16816(acc[fm][fn], al[fm], bh2);
                }
            }
        }
        __syncthreads();
        cur ^= 1;
    }

    #pragma unroll
    for (int fm = 0; fm < 4; fm++) {
        #pragma unroll
        for (int fn = 0; fn < 4; fn++) {
            const int row = m0 + wm + fm * 16 + (lane >> 2);
            const int col = n0 + wn + fn * 8 + (lane & 3) * 2;
            float b0, b1, b0b, b1b;
            if (BIAS_COL) { b0 = bias[col]; b1 = bias[col + 1]; b0b = b0; b1b = b1; }
            else          { b0 = bias[row]; b1 = b0; b0b = bias[row + 8]; b1b = b0b; }
            float v0 = acc[fm][fn][0] + b0,  v1 = acc[fm][fn][1] + b1;
            float v2 = acc[fm][fn][2] + b0b, v3 = acc[fm][fn][3] + b1b;
            if (SPLIT_OUT) {
                __nv_bfloat16 h0, l0, h1, l1;
                split_bf16(v0, h0, l0); split_bf16(v1, h1, l1);
                *(__nv_bfloat162*)(Ch + (long)row * N + col) = __halves2bfloat162(h0, h1);
                *(__nv_bfloat162*)(Cl + (long)row * N + col) = __halves2bfloat162(l0, l1);
                split_bf16(v2, h0, l0); split_bf16(v3, h1, l1);
                *(__nv_bfloat162*)(Ch + (long)(row + 8) * N + col) = __halves2bfloat162(h0, h1);
                *(__nv_bfloat162*)(Cl + (long)(row + 8) * N + col) = __halves2bfloat162(l0, l1);
            } else {
                *(float2*)(C + (long)row * N + col)       = make_float2(v0, v1);
                *(float2*)(C + (long)(row + 8) * N + col) = make_float2(v2, v3);
            }
        }
    }
}

// ---------------------------------------------------------------------------
// Tensor-core flash attention, 2-CTA/SM version.
// Grid (16,16,4) = (q-tile of 64, head, batch). 128 threads = 4 warps; each
// warp owns 16 q-rows (warp-local softmax). K/V tiles of 64 keys, 2-stage
// cp.async double buffer. Smem = 92160 B -> two CTAs co-resident per SM.
// Precision identical to R11: QK bf16x3, P bf16, V hi/lo.
// ---------------------------------------------------------------------------
#define AT_STR 72
#define AT_QSZ (64 * AT_STR)          // one 64x64 matrix (padded), halves

__global__ __launch_bounds__(128)
void attn_mma(const __nv_bfloat16* __restrict__ qh_g, const __nv_bfloat16* __restrict__ ql_g,
              __nv_bfloat16* __restrict__ oh, __nv_bfloat16* __restrict__ ol)
{
    extern __shared__ __align__(16) __nv_bfloat16 sm[];
    __nv_bfloat16* Qh = sm;                       // [0, AT_QSZ)
    __nv_bfloat16* Ql = sm + AT_QSZ;              // [AT_QSZ, 2*AT_QSZ)
    // stage s (s=0,1): base = 2*AT_QSZ + s*4*AT_QSZ: [Kh][Kl][Vh][Vl]

    const int tid  = threadIdx.x;
    const int lane = tid & 31;
    const int warp = tid >> 5;                    // 0..3
    const int qc = blockIdx.x;                    // 0..15
    const int h  = blockIdx.y;
    const int b  = blockIdx.z;
    const int n0 = qc * 64;

    const long boff = (long)b * 1024 * 3072 + h * 64;

    auto issueKV = [&](int kt, int st) {
        __nv_bfloat16* base = sm + 2 * AT_QSZ + st * 4 * AT_QSZ;
        const int k0 = kt * 64;
        #pragma unroll
        for (int j = 0; j < 4; j++) {
            const int idx = j * 128 + tid;        // 0..511
            const int rr = idx >> 3;              // 0..63
            const int c8 = (idx & 7) * 8;
            const long grow = boff + (long)(k0 + rr) * 3072;
            const int soff = rr * AT_STR + c8;
            cpa16(cvta_s(base + soff),               qh_g + grow + 1024 + c8);  // Kh
            cpa16(cvta_s(base + AT_QSZ + soff),      ql_g + grow + 1024 + c8);  // Kl
            cpa16(cvta_s(base + 2 * AT_QSZ + soff),  qh_g + grow + 2048 + c8);  // Vh
            cpa16(cvta_s(base + 3 * AT_QSZ + soff),  ql_g + grow + 2048 + c8);  // Vl
        }
    };

    issueKV(0, 0); CP_COMMIT();

    // Q staging with exact 2^-3 scale
    {
        const __nv_bfloat162 s2 = __floats2bfloat162_rn(0.125f, 0.125f);
        for (int idx = tid; idx < 512; idx += 128) {
            const int rr = idx >> 3;
            const int c8 = (idx & 7) * 8;
            const long grow = boff + (long)(n0 + rr) * 3072;
            uint4 vh = *(const uint4*)(qh_g + grow + c8);
            uint4 vl = *(const uint4*)(ql_g + grow + c8);
            __nv_bfloat162* ph = (__nv_bfloat162*)&vh;
            __nv_bfloat162* pl = (__nv_bfloat162*)&vl;
            #pragma unroll
            for (int e = 0; e < 4; e++) { ph[e] = __hmul2(ph[e], s2); pl[e] = __hmul2(pl[e], s2); }
            *(uint4*)(Qh + rr * AT_STR + c8) = vh;
            *(uint4*)(Ql + rr * AT_STR + c8) = vl;
        }
    }
    __syncthreads();

    uint32_t qh[4][4], ql[4][4];
    #pragma unroll
    for (int ks = 0; ks < 4; ks++) {
        const int row = warp * 16 + (lane & 15);
        const int col = ks * 16 + (lane >> 4) * 8;
        LDMX4(qh[ks], cvta_s(Qh + row * AT_STR + col));
        LDMX4(ql[ks], cvta_s(Ql + row * AT_STR + col));
    }

    float o[8][4];
    #pragma unroll
    for (int i = 0; i < 8; i++)
        #pragma unroll
        for (int e = 0; e < 4; e++) o[i][e] = 0.f;
    float mrow[2] = {-1e30f, -1e30f};
    float lrow[2] = {0.f, 0.f};

    int st = 0;
    for (int kt = 0; kt < 16; kt++) {
        const bool more = kt < 15;
        if (more) { issueKV(kt + 1, st ^ 1); CP_COMMIT(); }
        if (more) CP_WAIT(1); else CP_WAIT(0);
        __syncthreads();

        const __nv_bfloat16* Kh = sm + 2 * AT_QSZ + st * 4 * AT_QSZ;
        const __nv_bfloat16* Kl = Kh + AT_QSZ;
        const __nv_bfloat16* Vh = Kh + 2 * AT_QSZ;
        const __nv_bfloat16* Vl = Kh + 3 * AT_QSZ;

        // S = Q K^T over 64 keys: s[8][4]
        float s[8][4];
        #pragma unroll
        for (int fn = 0; fn < 8; fn++)
            #pragma unroll
            for (int e = 0; e < 4; e++) s[fn][e] = 0.f;

        #pragma unroll
        for (int fn = 0; fn < 8; fn++) {
            #pragma unroll
            for (int ks = 0; ks < 4; ks++) {
                uint32_t kh2[2], kl2[2];
                const int row = fn * 8 + (lane & 7);
                const int col = ks * 16 + ((lane >> 3) & 1) * 8;
                LDMX2(kh2, cvta_s(Kh + row * AT_STR + col));
                LDMX2(kl2, cvta_s(Kl + row * AT_STR + col));
                MMA16816(s[fn], qh[ks], kh2);
                MMA16816(s[fn], qh[ks], kl2);
                MMA16816(s[fn], ql[ks], kh2);
            }
        }

        // online softmax (warp-local rows; quad lanes share a row)
        #pragma unroll
        for (int h2 = 0; h2 < 2; h2++) {
            float mx = mrow[h2];
            #pragma unroll
            for (int fn = 0; fn < 8; fn++)
                mx = fmaxf(mx, fmaxf(s[fn][2 * h2], s[fn][2 * h2 + 1]));
            mx = fmaxf(mx, __shfl_xor_sync(0xffffffffu, mx, 1));
            mx = fmaxf(mx, __shfl_xor_sync(0xffffffffu, mx, 2));
            const float alpha = __expf(mrow[h2] - mx);
            mrow[h2] = mx;
            float sum = 0.f;
            #pragma unroll
            for (int fn = 0; fn < 8; fn++) {
                float p0 = __expf(s[fn][2 * h2] - mx);
                float p1 = __expf(s[fn][2 * h2 + 1] - mx);
                s[fn][2 * h2] = p0; s[fn][2 * h2 + 1] = p1;
                sum += p0 + p1;
            }
            sum += __shfl_xor_sync(0xffffffffu, sum, 1);
            sum += __shfl_xor_sync(0xffffffffu, sum, 2);
            lrow[h2] = lrow[h2] * alpha + sum;
            #pragma unroll
            for (int fn = 0; fn < 8; fn++) {
                o[fn][2 * h2]     *= alpha;
                o[fn][2 * h2 + 1] *= alpha;
            }
        }

        // pack P (C-frag -> A-frag, bf16): 64 keys = 4 k16 fragments
        uint32_t pk[4][4];
        #pragma unroll
        for (int kf = 0; kf < 4; kf++) {
            pk[kf][0] = pack_bf2(s[2 * kf][0],     s[2 * kf][1]);
            pk[kf][1] = pack_bf2(s[2 * kf][2],     s[2 * kf][3]);
            pk[kf][2] = pack_bf2(s[2 * kf + 1][0], s[2 * kf + 1][1]);
            pk[kf][3] = pack_bf2(s[2 * kf + 1][2], s[2 * kf + 1][3]);
        }

        // O += P V
        #pragma unroll
        for (int kf = 0; kf < 4; kf++) {
            const int row = kf * 16 + (lane & 7) + ((lane >> 3) & 1) * 8;
            #pragma unroll
            for (int fn = 0; fn < 8; fn++) {
                uint32_t vh2[2], vl2[2];
                LDMX2T(vh2, cvta_s(Vh + row * AT_STR + fn * 8));
                LDMX2T(vl2, cvta_s(Vl + row * AT_STR + fn * 8));
                MMA16816(o[fn], pk[kf], vh2);
                MMA16816(o[fn], pk[kf], vl2);
            }
        }
        __syncthreads();
        st ^= 1;
    }

    const float inv0 = 1.f / lrow[0];
    const float inv1 = 1.f / lrow[1];
    const int r0 = n0 + warp * 16 + (lane >> 2);
    const int cb = h * 64 + (lane & 3) * 2;
    #pragma unroll
    for (int fn = 0; fn < 8; fn++) {
        const int col = cb + fn * 8;
        float v0 = o[fn][0] * inv0, v1 = o[fn][1] * inv0;
        float v2 = o[fn][2] * inv1, v3 = o[fn][3] * inv1;
        __nv_bfloat16 h0, l0, h1, l1;
        split_bf16(v0, h0, l0); split_bf16(v1, h1, l1);
        *(__nv_bfloat162*)(oh + ((long)b * 1024 + r0) * 1024 + col) = __halves2bfloat162(h0, h1);
        *(__nv_bfloat162*)(ol + ((long)b * 1024 + r0) * 1024 + col) = __halves2bfloat162(l0, l1);
        split_bf16(v2, h0, l0); split_bf16(v3, h1, l1);
        *(__nv_bfloat162*)(oh + ((long)b * 1024 + r0 + 8) * 1024 + col) = __halves2bfloat162(h0, h1);
        *(__nv_bfloat162*)(ol + ((long)b * 1024 + r0 + 8) * 1024 + col) = __halves2bfloat162(l0, l1);
    }
}

// ---------------------------------------------------------------------------
// Launch
// ---------------------------------------------------------------------------
extern "C" void kernel_launch(void* const* d_in, const int* in_sizes, int n_in,
                              void* d_out, int out_size)
{
    (void)in_sizes; (void)n_in; (void)out_size;
    const float* x   = (const float*)d_in[0];
    const float* Wq0 = (const float*)d_in[1];
    const float* bq0 = (const float*)d_in[2];
    const float* Wq1 = (const float*)d_in[3];
    const float* bq1 = (const float*)d_in[4];
    const float* Wp0 = (const float*)d_in[5];
    const float* bp0 = (const float*)d_in[6];
    const float* Wp1 = (const float*)d_in[7];
    const float* bp1 = (const float*)d_in[8];
    float* out = (float*)d_out;

    __nv_bfloat16 *xh, *xl, *w0h, *w0l, *w1h, *w1l, *p0h, *p0l, *p1h, *p1l;
    __nv_bfloat16 *t1h, *t1l, *qh, *ql, *ah, *al, *t2h, *t2l;
    cudaGetSymbolAddress((void**)&xh,  g_xh);  cudaGetSymbolAddress((void**)&xl,  g_xl);
    cudaGetSymbolAddress((void**)&w0h, g_w0h); cudaGetSymbolAddress((void**)&w0l, g_w0l);
    cudaGetSymbolAddress((void**)&w1h, g_w1h); cudaGetSymbolAddress((void**)&w1l, g_w1l);
    cudaGetSymbolAddress((void**)&p0h, g_p0h); cudaGetSymbolAddress((void**)&p0l, g_p0l);
    cudaGetSymbolAddress((void**)&p1h, g_p1h); cudaGetSymbolAddress((void**)&p1l, g_p1l);
    cudaGetSymbolAddress((void**)&t1h, g_t1h); cudaGetSymbolAddress((void**)&t1l, g_t1l);
    cudaGetSymbolAddress((void**)&qh,  g_qh);  cudaGetSymbolAddress((void**)&ql,  g_ql);
    cudaGetSymbolAddress((void**)&ah,  g_ah);  cudaGetSymbolAddress((void**)&al,  g_al);
    cudaGetSymbolAddress((void**)&t2h, g_t2h); cudaGetSymbolAddress((void**)&t2l, g_t2l);

    const int smem_bt = (2 * (2 * 128 * 40 + 2 * 128 * 40)) * 2;   // 81920 B
    const int smem_nn = (2 * (2 * 128 * 40 + 2 * 32 * 136)) * 2;   // 75776 B
    cudaFuncSetAttribute(bgemm<true, true, true>,
                         cudaFuncAttributeMaxDynamicSharedMemorySize, smem_bt);
    cudaFuncSetAttribute(bgemm<true, true, false>,
                         cudaFuncAttributeMaxDynamicSharedMemorySize, smem_bt);
    cudaFuncSetAttribute(bgemm<false, false, true>,
                         cudaFuncAttributeMaxDynamicSharedMemorySize, smem_nn);

    const int attn_smem = 10 * AT_QSZ * 2;                         // 92160 B
    cudaFuncSetAttribute(attn_mma,
                         cudaFuncAttributeMaxDynamicSharedMemorySize, attn_smem);

    dim3 blk(256);
    const long P = 1024L * 1024;

    // 0) merged pre-split (x + all four weights), one launch
    presplit5<<<10240, blk>>>((const float4*)x, (const float4*)Wq0, (const float4*)Wq1,
                              (const float4*)Wp0, (const float4*)Wp1,
                              (__nv_bfloat162*)xh,  (__nv_bfloat162*)xl,
                              (__nv_bfloat162*)w0h, (__nv_bfloat162*)w0l,
                              (__nv_bfloat162*)w1h, (__nv_bfloat162*)w1l,
                              (__nv_bfloat162*)p0h, (__nv_bfloat162*)p0l,
                              (__nv_bfloat162*)p1h, (__nv_bfloat162*)p1l);

    // 1) qkv seq-linear (NN): t1[b] = Wq0 @ x[b] + bq0
    bgemm<false, false, true><<<dim3(8, 8, 4), blk, smem_nn>>>(
        w0h, w0l, xh, xl, bq0, nullptr, t1h, t1l, 1024, 1024, 1024, 0, P, P);

    // 2) qkv channel-linear (BT): qkv = t1 @ Wq1^T + bq1
    bgemm<true, true, true><<<dim3(24, 32, 1), blk, smem_bt>>>(
        t1h, t1l, w1h, w1l, bq1, nullptr, qh, ql, 4096, 3072, 1024, 0, 0, 0);

    // 3) flash attention (2 CTAs/SM)
    attn_mma<<<dim3(16, 16, 4), dim3(128), attn_smem>>>(qh, ql, ah, al);

    // 4) proj seq-linear (NN)
    bgemm<false, false, true><<<dim3(8, 8, 4), blk, smem_nn>>>(
        p0h, p0l, ah, al, bp0, nullptr, t2h, t2l, 1024, 1024, 1024, 0, P, P);

    // 5) proj channel-linear (BT) -> fp32 output
    bgemm<true, true, false><<<dim3(8, 32, 1), blk, smem_bt>>>(
        t2h, t2l, p1h, p1l, bp1, out, nullptr, nullptr, 4096, 1024, 1024, 0, 0, 0);
}